// round 12
// baseline (speedup 1.0000x reference)
#include <cuda_runtime.h>
#include <cuda_bf16.h>
#include <cuda_fp16.h>
#include <math.h>
#include <stdint.h>

// ---------------- static scratch (allocation-free) ----------------
#define UMAX 200000
__device__ int   g_winner[UMAX * 8];
__device__ int   g_selrows[UMAX];
__device__ int   g_bsum[256];
__device__ __align__(16) __half g_wt_h[256 * 512];
__device__ __align__(16) __half g_w2t_h[64 * 256];
__device__ __align__(16) __half g_z1h[(size_t)UMAX * 256];
__device__ __align__(16) float g_stats1[512];   // sum[256] | sumsq[256]
__device__ __align__(16) float g_stats2[128];   // sum[64]  | sumsq[64]
__device__ __align__(16) float g_bn1sc[256];
__device__ __align__(16) float g_bn1sh[256];
__device__ __align__(16) float g_bn2sc[64];
__device__ __align__(16) float g_bn2sh[64];

__device__ __forceinline__ uint32_t smem_u32(const void* p) {
    uint32_t a;
    asm("{ .reg .u64 t; cvta.to.shared.u64 t, %1; cvt.u32.u64 %0, t; }" : "=r"(a) : "l"(p));
    return a;
}

// ---------------- init + weight prep (merged) ----------------
__global__ void k_init(int nwin, const float* __restrict__ W1, const float* __restrict__ W2) {
    int i = blockIdx.x * blockDim.x + threadIdx.x;
    if (i < nwin) g_winner[i] = -1;
    if (i < 512)  g_stats1[i] = 0.f;
    if (i < 128)  g_stats2[i] = 0.f;
    if (i < 131072) {
        int n = i >> 9, k = i & 511;
        g_wt_h[i] = __float2half(W1[(size_t)k * 256 + n]);
    }
    if (i < 16384) {
        int n = i >> 8, k = i & 255;
        g_w2t_h[i] = __float2half(W2[(size_t)k * 64 + n]);
    }
}

// ---------------- scatter: last-write-wins via max voxel index ----------------
__global__ void k_scatter(const int* __restrict__ coords, const int* __restrict__ inv, int Nv) {
    int i = blockIdx.x * blockDim.x + threadIdx.x;
    if (i < Nv) {
        int z = coords[(size_t)i * 4 + 1];
        int u = inv[i];
        atomicMax(&g_winner[(size_t)u * 8 + z], i);
    }
}

// ---------------- ordered compaction of rows with cnt>=2 ----------------
__global__ void k_count(const int* __restrict__ cnt, int U) {
    __shared__ int s[256];
    int base = blockIdx.x * 1024;
    int c = 0;
    for (int t = threadIdx.x; t < 1024; t += 256) {
        int u = base + t;
        if (u < U && cnt[u] >= 2) c++;
    }
    s[threadIdx.x] = c;
    __syncthreads();
    for (int o = 128; o > 0; o >>= 1) {
        if (threadIdx.x < o) s[threadIdx.x] += s[threadIdx.x + o];
        __syncthreads();
    }
    if (threadIdx.x == 0) g_bsum[blockIdx.x] = s[0];
}

__global__ void k_scan2(int nb) {
    __shared__ int s[256];
    int t = threadIdx.x;
    int v = (t < nb) ? g_bsum[t] : 0;
    s[t] = v;
    __syncthreads();
    for (int o = 1; o < 256; o <<= 1) {
        int u = (t >= o) ? s[t - o] : 0;
        __syncthreads();
        s[t] += u;
        __syncthreads();
    }
    if (t < nb) g_bsum[t] = s[t] - v;   // exclusive
}

__global__ void k_compact(const int* __restrict__ cnt, int U) {
    __shared__ int s[256];
    int tid = threadIdx.x;
    int base = blockIdx.x * 1024 + tid * 4;
    int flags[4]; int c = 0;
    for (int q = 0; q < 4; q++) {
        int u = base + q;
        flags[q] = (u < U && cnt[u] >= 2) ? 1 : 0;
        c += flags[q];
    }
    s[tid] = c;
    __syncthreads();
    for (int o = 1; o < 256; o <<= 1) {
        int v = (tid >= o) ? s[tid - o] : 0;
        __syncthreads();
        s[tid] += v;
        __syncthreads();
    }
    int off = g_bsum[blockIdx.x] + s[tid] - c;
    for (int q = 0; q < 4; q++) {
        if (flags[q]) g_selrows[off++] = base + q;
    }
}

// ---------------- common mma macros ----------------
#define LDSM4(R0, R1, R2, R3, ADDR) \
    asm volatile("ldmatrix.sync.aligned.m8n8.x4.shared.b16 {%0,%1,%2,%3}, [%4];" \
                 : "=r"(R0), "=r"(R1), "=r"(R2), "=r"(R3) : "r"(ADDR))

#define MMA16816F16(D, A, B) \
    asm volatile("mma.sync.aligned.m16n8k16.row.col.f32.f16.f16.f32 " \
                 "{%0,%1,%2,%3}, {%4,%5,%6,%7}, {%8,%9}, {%0,%1,%2,%3};" \
                 : "+f"((D)[0]), "+f"((D)[1]), "+f"((D)[2]), "+f"((D)[3]) \
                 : "r"((A)[0]), "r"((A)[1]), "r"((A)[2]), "r"((A)[3]), \
                   "r"((B)[0]), "r"((B)[1]))

__device__ __forceinline__ void cp16(uint32_t saddr, const void* gaddr) {
    asm volatile("cp.async.cg.shared.global [%0], [%1], 16;"
                 :: "r"(saddr), "l"(gaddr));
}

// ---------------- FUSED: per-row CBAM (phase 1, A->smem) + GEMM1 (phase 2) + bn1 stats ----------------
// A tile: 64 rows x 512 fp16, pitch 1040B (conflict-free ldmatrix).
// B: K chunks of 32, double-buffered, pitch 80B; phase-1 scratch overlaid on B region.
#define F_APITCH  1040
#define F_A_OFF   0
#define F_B_OFF   66560
#define F_BSTAGE  20480
#define F_BPITCH  80
#define F_SMEM    (66560 + 2 * 20480)
// phase-1 scratch float offsets (from F_B_OFF)
#define P1_SW1    0
#define P1_SB1    160
#define P1_SB2    192
#define P1_SCW1   256
#define P1_SCW2   768
#define P1_SCONV  1280
#define P1_SFEAT  1296
#define P1_SHID   1616

__global__ void __launch_bounds__(256)
k_fused(const float* __restrict__ vf,
        const float* __restrict__ w1, const float* __restrict__ b1,
        const float* __restrict__ w2g, const float* __restrict__ b2,
        const float* __restrict__ caw1, const float* __restrict__ caw2,
        const float* __restrict__ saconv, int M)
{
    extern __shared__ __align__(16) char dsm[];
    uint32_t sbase = smem_u32(dsm);
    float* p1 = (float*)(dsm + F_B_OFF);

    const unsigned FULL = 0xffffffffu;
    int tid  = threadIdx.x;
    int wid  = tid >> 5;
    int lane = tid & 31;
    int row0 = blockIdx.x * 64;

    // ---------- phase 1: CBAM rows -> A smem tile ----------
    for (int i = tid; i < 160; i += 256) p1[P1_SW1 + i] = w1[i];
    if (tid < 32) p1[P1_SB1 + tid] = b1[tid];
    if (tid < 64) p1[P1_SB2 + tid] = b2[tid];
    for (int i = tid; i < 512; i += 256) p1[P1_SCW1 + i] = caw1[i];
    for (int i = tid; i < 512; i += 256) p1[P1_SCW2 + i] = caw2[i];
    if (tid < 14) p1[P1_SCONV + tid] = saconv[tid];

    float w2a[32], w2b[32];
#pragma unroll
    for (int k = 0; k < 32; k++) {
        w2a[k] = w2g[k * 64 + lane];
        w2b[k] = w2g[k * 64 + lane + 32];
    }
    __syncthreads();

    for (int r = 0; r < 8; r++) {
        int j = row0 + wid * 8 + r;
        int valid = (j < M);
        int arow = wid * 8 + r;
        int u = valid ? g_selrows[j] : 0;
        int wv = (valid && lane < 8) ? g_winner[(size_t)u * 8 + lane] : -1;

#pragma unroll
        for (int q = 0; q < 2; q++) {
            int t = lane + q * 32;
            int tv = (t < 40);
            int zz = tv ? (t / 5) : 0;
            int f  = t - zz * 5;
            int w = __shfl_sync(FULL, wv, zz);
            if (tv) p1[P1_SFEAT + wid * 40 + t] = (w >= 0) ? vf[(size_t)w * 5 + f] : 0.f;
        }
        __syncwarp();

#pragma unroll
        for (int z = 0; z < 8; z++) {
            float a = p1[P1_SB1 + lane];
#pragma unroll
            for (int f = 0; f < 5; f++)
                a += p1[P1_SFEAT + wid * 40 + z * 5 + f] * p1[P1_SW1 + f * 32 + lane];
            p1[P1_SHID + wid * 256 + z * 32 + lane] = fmaxf(a, 0.f);
        }
        __syncwarp();

        float x0[8], x1[8];
#pragma unroll
        for (int z = 0; z < 8; z++) {
            float a0 = p1[P1_SB2 + lane], a1 = p1[P1_SB2 + lane + 32];
            const float* hz = &p1[P1_SHID + wid * 256 + z * 32];
#pragma unroll
            for (int k4 = 0; k4 < 8; k4++) {
                float4 h = *(const float4*)(hz + k4 * 4);
                a0 += h.x * w2a[k4 * 4] + h.y * w2a[k4 * 4 + 1] + h.z * w2a[k4 * 4 + 2] + h.w * w2a[k4 * 4 + 3];
                a1 += h.x * w2b[k4 * 4] + h.y * w2b[k4 * 4 + 1] + h.z * w2b[k4 * 4 + 2] + h.w * w2b[k4 * 4 + 3];
            }
            x0[z] = a0; x1[z] = a1;
        }

        float m0 = 0.f, m1 = 0.f, q0 = -3.4e38f, q1 = -3.4e38f;
#pragma unroll
        for (int z = 0; z < 8; z++) {
            m0 += x0[z]; m1 += x1[z];
            q0 = fmaxf(q0, x0[z]); q1 = fmaxf(q1, x1[z]);
        }
        m0 *= 0.125f; m1 *= 0.125f;

        float s8[8];
#pragma unroll
        for (int r8 = 0; r8 < 8; r8++) {
            float pm = m0 * p1[P1_SCW1 + lane * 8 + r8] + m1 * p1[P1_SCW1 + (lane + 32) * 8 + r8];
            float px = q0 * p1[P1_SCW1 + lane * 8 + r8] + q1 * p1[P1_SCW1 + (lane + 32) * 8 + r8];
#pragma unroll
            for (int o = 16; o > 0; o >>= 1) {
                pm += __shfl_xor_sync(FULL, pm, o);
                px += __shfl_xor_sync(FULL, px, o);
            }
            s8[r8] = fmaxf(pm, 0.f) + fmaxf(px, 0.f);
        }

        float a0 = 0.f, a1 = 0.f;
#pragma unroll
        for (int r8 = 0; r8 < 8; r8++) {
            a0 += s8[r8] * p1[P1_SCW2 + r8 * 64 + lane];
            a1 += s8[r8] * p1[P1_SCW2 + r8 * 64 + lane + 32];
        }
        float ca0 = 1.f / (1.f + expf(-a0));
        float ca1 = 1.f / (1.f + expf(-a1));
#pragma unroll
        for (int z = 0; z < 8; z++) { x0[z] *= ca0; x1[z] *= ca1; }

        float szm[8], szx[8];
#pragma unroll
        for (int z = 0; z < 8; z++) {
            float s = x0[z] + x1[z];
            float m = fmaxf(x0[z], x1[z]);
#pragma unroll
            for (int o = 16; o > 0; o >>= 1) {
                s += __shfl_xor_sync(FULL, s, o);
                m = fmaxf(m, __shfl_xor_sync(FULL, m, o));
            }
            szm[z] = s * (1.f / 64.f);
            szx[z] = m;
        }

        float sav = 0.f;
        if (lane < 8) {
            float acc = 0.f;
#pragma unroll
            for (int t = 0; t < 7; t++) {
                int p = lane + t - 3;
                if (p >= 0 && p < 8) acc += szm[p] * p1[P1_SCONV + t] + szx[p] * p1[P1_SCONV + 7 + t];
            }
            sav = 1.f / (1.f + expf(-acc));
        }
        float sa[8];
#pragma unroll
        for (int z = 0; z < 8; z++) sa[z] = __shfl_sync(FULL, sav, z);

        // write A tile row (smem): cols [c*8+z], fp16; zeros for invalid rows
        uint32_t ph[4];
#pragma unroll
        for (int z2 = 0; z2 < 4; z2++) {
            __half2 h2 = __floats2half2_rn(x0[2 * z2] * sa[2 * z2], x0[2 * z2 + 1] * sa[2 * z2 + 1]);
            ph[z2] = valid ? *(uint32_t*)&h2 : 0u;
        }
        *(uint4*)(dsm + F_A_OFF + arow * F_APITCH + lane * 16) = *(uint4*)ph;
#pragma unroll
        for (int z2 = 0; z2 < 4; z2++) {
            __half2 h2 = __floats2half2_rn(x1[2 * z2] * sa[2 * z2], x1[2 * z2 + 1] * sa[2 * z2 + 1]);
            ph[z2] = valid ? *(uint32_t*)&h2 : 0u;
        }
        *(uint4*)(dsm + F_A_OFF + arow * F_APITCH + 512 + lane * 16) = *(uint4*)ph;
        __syncwarp();
    }
    __syncthreads();   // A tile complete; phase-1 scratch dead

    // ---------- phase 2: GEMM 64x256x512, A in smem, B streamed ----------
    int wm = wid & 1;      // 2 m-warps (32 rows)
    int wn = wid >> 1;     // 4 n-warps (64 cols)

    auto load_bchunk = [&](int c) {
        uint32_t st = sbase + F_B_OFF + (uint32_t)(c & 1) * F_BSTAGE;
#pragma unroll
        for (int it = 0; it < 4; it++) {
            int task = tid + it * 256;
            int n = task >> 2, seg = task & 3;
            cp16(st + n * F_BPITCH + seg * 16, g_wt_h + (size_t)n * 512 + c * 32 + seg * 8);
        }
        asm volatile("cp.async.commit_group;");
    };

    load_bchunk(0);

    uint32_t aRow  = (uint32_t)(wm * 32 + (lane & 15));
    uint32_t aColB = (uint32_t)((lane >> 4) * 16);
    uint32_t bRowB = (uint32_t)(((lane >> 4) & 1) * 8 + (lane & 7));
    uint32_t bColB = (uint32_t)(((lane >> 3) & 1) * 16);

    float acc[2][8][4] = {};

    for (int c = 0; c < 16; c++) {
        if (c < 15) load_bchunk(c + 1);
        if (c < 15) { asm volatile("cp.async.wait_group 1;"); }
        else        { asm volatile("cp.async.wait_group 0;"); }
        __syncthreads();

        uint32_t stB = sbase + F_B_OFF + (uint32_t)(c & 1) * F_BSTAGE;
#pragma unroll
        for (int kk = 0; kk < 2; kk++) {
            uint32_t kbA = (uint32_t)(c * 64 + kk * 32);
            uint32_t kbB = (uint32_t)(kk * 32);
            uint32_t ah[2][4];
#pragma unroll
            for (int mi = 0; mi < 2; mi++) {
                uint32_t ad = sbase + F_A_OFF + (aRow + mi * 16) * F_APITCH + kbA + aColB;
                LDSM4(ah[mi][0], ah[mi][1], ah[mi][2], ah[mi][3], ad);
            }
            uint32_t bh[8][2];
#pragma unroll
            for (int nh = 0; nh < 4; nh++) {
                uint32_t bd = stB + (wn * 64 + nh * 16 + bRowB) * F_BPITCH + kbB + bColB;
                uint32_t t0, t1, t2, t3;
                LDSM4(t0, t1, t2, t3, bd);
                bh[nh * 2][0] = t0; bh[nh * 2][1] = t1;
                bh[nh * 2 + 1][0] = t2; bh[nh * 2 + 1][1] = t3;
            }
#pragma unroll
            for (int mi = 0; mi < 2; mi++) {
#pragma unroll
                for (int ni = 0; ni < 8; ni++) {
                    MMA16816F16(acc[mi][ni], ah[mi], bh[ni]);
                }
            }
        }
        __syncthreads();
    }

    // epilogue: z1 fp16 store + fused bn1 stats
#pragma unroll
    for (int mi = 0; mi < 2; mi++) {
#pragma unroll
        for (int ni = 0; ni < 8; ni++) {
            int grow = row0 + wm * 32 + mi * 16 + (lane >> 2);
            int gcol = wn * 64 + ni * 8 + (lane & 3) * 2;
            if (grow < M) {
                __half2 h = __floats2half2_rn(acc[mi][ni][0], acc[mi][ni][1]);
                *(uint32_t*)(g_z1h + (size_t)grow * 256 + gcol) = *(uint32_t*)&h;
            }
            if (grow + 8 < M) {
                __half2 h = __floats2half2_rn(acc[mi][ni][2], acc[mi][ni][3]);
                *(uint32_t*)(g_z1h + (size_t)(grow + 8) * 256 + gcol) = *(uint32_t*)&h;
            }
        }
    }

#pragma unroll
    for (int ni = 0; ni < 8; ni++) {
#pragma unroll
        for (int jj = 0; jj < 2; jj++) {
            float s = 0.f, s2 = 0.f;
#pragma unroll
            for (int mi = 0; mi < 2; mi++) {
                float v0 = acc[mi][ni][jj], v1 = acc[mi][ni][jj + 2];
                s += v0 + v1; s2 += v0 * v0 + v1 * v1;
            }
#pragma unroll
            for (int o = 4; o <= 16; o <<= 1) {
                s  += __shfl_xor_sync(FULL, s, o);
                s2 += __shfl_xor_sync(FULL, s2, o);
            }
            if ((lane >> 2) == 0) {
                int col = wn * 64 + ni * 8 + (lane & 3) * 2 + jj;
                atomicAdd(&g_stats1[col], s);
                atomicAdd(&g_stats1[256 + col], s2);
            }
        }
    }
}

__global__ void k_bnp(const float* __restrict__ g, const float* __restrict__ b,
                      int C, float invM, int which) {
    int c = blockIdx.x * blockDim.x + threadIdx.x;
    if (c < C) {
        const float* st = which ? g_stats2 : g_stats1;
        float* sc = which ? g_bn2sc : g_bn1sc;
        float* sh = which ? g_bn2sh : g_bn1sh;
        float mu  = st[c] * invM;
        float var = st[C + c] * invM - mu * mu;
        float s = g[c] * rsqrtf(var + 0.001f);
        sc[c] = s;
        sh[c] = b[c] - mu * s;
    }
}

// ---------------- GEMM2 (mma.sync fp16 single-pass): out = relu(bn1(z1)) @ W2 + fused bn2 stats ----------------
#define G2_PITCHB  144
#define G2_BPITCH  528
#define G2_A_OFF   0
#define G2_B_OFF   18432
#define G2_SMEM    (18432 + 64 * 528)

__global__ void __launch_bounds__(256, 2)
k_gemm2_mma(float* __restrict__ out, int M) {
    extern __shared__ __align__(16) char dsm2[];
    uint32_t sbase = smem_u32(dsm2);
    __shared__ float ss[128];
    const unsigned FULL = 0xffffffffu;

    int tid  = threadIdx.x;
    int lane = tid & 31;
    int wid  = tid >> 5;
    int row0 = blockIdx.x * 128;

    if (tid < 128) ss[tid] = 0.f;

    {
        int n = tid >> 2;
        int kg = (tid & 3) * 64;
        const uint4* gh = (const uint4*)(g_w2t_h + (size_t)n * 256 + kg);
        uint32_t off = (uint32_t)(n * G2_BPITCH + kg * 2);
#pragma unroll
        for (int q = 0; q < 8; q++)
            *(uint4*)(dsm2 + G2_B_OFF + off + q * 16) = gh[q];
    }

    float acc[8][4] = {};

    uint32_t aRow  = (uint32_t)(wid * 16 + (lane & 15));
    uint32_t aColB = (uint32_t)((lane >> 4) * 16);
    uint32_t bRowB = (uint32_t)(((lane >> 4) & 1) * 8 + (lane & 7));
    uint32_t bColB = (uint32_t)(((lane >> 3) & 1) * 16);

    for (int c = 0; c < 4; c++) {
        __syncthreads();
        {
            int f4 = tid & 3;
            int colb = f4 * 16;
#pragma unroll
            for (int half = 0; half < 2; half++) {
                int r = (tid >> 2) + half * 64;
                int gr = row0 + r;
                uint32_t hv[8] = {};
                if (gr < M) {
                    const uint4* src = (const uint4*)(g_z1h + (size_t)gr * 256 + c * 64 + colb);
                    *(uint4*)&hv[0] = src[0];
                    *(uint4*)&hv[4] = src[1];
                }
                uint32_t outp[8];
#pragma unroll
                for (int p = 0; p < 8; p++) {
                    __half2 h2 = *(__half2*)&hv[p];
                    float2 v = __half22float2(h2);
                    int col = c * 64 + colb + p * 2;
                    float vsc0 = g_bn1sc[col],     vsh0 = g_bn1sh[col];
                    float vsc1 = g_bn1sc[col + 1], vsh1 = g_bn1sh[col + 1];
                    float y0 = (gr < M) ? fmaxf(v.x * vsc0 + vsh0, 0.f) : 0.f;
                    float y1 = (gr < M) ? fmaxf(v.y * vsc1 + vsh1, 0.f) : 0.f;
                    __half2 o = __floats2half2_rn(y0, y1);
                    outp[p] = *(uint32_t*)&o;
                }
                uint32_t off = (uint32_t)(r * G2_PITCHB + colb * 2);
                *(uint4*)(dsm2 + G2_A_OFF + off)      = *(uint4*)&outp[0];
                *(uint4*)(dsm2 + G2_A_OFF + off + 16) = *(uint4*)&outp[4];
            }
        }
        __syncthreads();

#pragma unroll
        for (int kk = 0; kk < 4; kk++) {
            uint32_t kb = (uint32_t)(kk * 32);
            uint32_t ah[4];
            {
                uint32_t ad = sbase + G2_A_OFF + aRow * G2_PITCHB + kb + aColB;
                LDSM4(ah[0], ah[1], ah[2], ah[3], ad);
            }
            uint32_t bh[8][2];
#pragma unroll
            for (int nh = 0; nh < 4; nh++) {
                uint32_t bd = sbase + G2_B_OFF + (nh * 16 + bRowB) * G2_BPITCH
                              + (uint32_t)(c * 128) + kb + bColB;
                uint32_t t0, t1, t2, t3;
                LDSM4(t0, t1, t2, t3, bd);
                bh[nh * 2][0] = t0; bh[nh * 2][1] = t1;
                bh[nh * 2 + 1][0] = t2; bh[nh * 2 + 1][1] = t3;
            }
#pragma unroll
            for (int ni = 0; ni < 8; ni++) {
                MMA16816F16(acc[ni], ah, bh[ni]);
            }
        }
    }

    int grow = row0 + wid * 16 + (lane >> 2);
#pragma unroll
    for (int ni = 0; ni < 8; ni++) {
        int gcol = ni * 8 + (lane & 3) * 2;
        if (grow < M)
            *(float2*)(out + (size_t)grow * 64 + gcol) = make_float2(acc[ni][0], acc[ni][1]);
        if (grow + 8 < M)
            *(float2*)(out + (size_t)(grow + 8) * 64 + gcol) = make_float2(acc[ni][2], acc[ni][3]);
    }

#pragma unroll
    for (int ni = 0; ni < 8; ni++) {
#pragma unroll
        for (int jj = 0; jj < 2; jj++) {
            float s = acc[ni][jj] + acc[ni][jj + 2];
            float s2 = acc[ni][jj] * acc[ni][jj] + acc[ni][jj + 2] * acc[ni][jj + 2];
#pragma unroll
            for (int o = 4; o <= 16; o <<= 1) {
                s  += __shfl_xor_sync(FULL, s, o);
                s2 += __shfl_xor_sync(FULL, s2, o);
            }
            if ((lane >> 2) == 0) {
                int col = ni * 8 + (lane & 3) * 2 + jj;
                atomicAdd(&ss[col], s);
                atomicAdd(&ss[64 + col], s2);
            }
        }
    }
    __syncthreads();
    if (tid < 128) atomicAdd(&g_stats2[tid], ss[tid]);
}

__global__ void k_final(float* __restrict__ out, int n) {
    int i = blockIdx.x * blockDim.x + threadIdx.x;
    if (i < n) {
        int c = i & 63;
        out[i] = fmaxf(out[i] * g_bn2sc[c] + g_bn2sh[c], 0.f);
    }
}

// ---------------- launcher ----------------
extern "C" void kernel_launch(void* const* d_in, const int* in_sizes, int n_in,
                              void* d_out, int out_size) {
    const float* vf      = (const float*)d_in[0];
    const int*   coords  = (const int*)d_in[1];
    const int*   inv     = (const int*)d_in[3];
    const int*   cnt     = (const int*)d_in[4];
    const float* up_w1   = (const float*)d_in[5];
    const float* up_b1   = (const float*)d_in[6];
    const float* up_w2   = (const float*)d_in[7];
    const float* up_b2   = (const float*)d_in[8];
    const float* ca_w1   = (const float*)d_in[9];
    const float* ca_w2   = (const float*)d_in[10];
    const float* sa_conv = (const float*)d_in[11];
    const float* bs_w1   = (const float*)d_in[12];
    const float* bn1_g   = (const float*)d_in[13];
    const float* bn1_b   = (const float*)d_in[14];
    const float* bs_w2   = (const float*)d_in[15];
    const float* bn2_g   = (const float*)d_in[16];
    const float* bn2_b   = (const float*)d_in[17];

    int Nv = in_sizes[0] / 5;
    int U  = in_sizes[2];
    int M  = out_size / 64;
    if (M <= 0) return;

    int nwin = U * 8;
    k_init<<<(nwin + 255) / 256, 256>>>(nwin, bs_w1, bs_w2);
    k_scatter<<<(Nv + 255) / 256, 256>>>(coords, inv, Nv);

    int NB = (U + 1023) / 1024;
    k_count<<<NB, 256>>>(cnt, U);
    k_scan2<<<1, 256>>>(NB);
    k_compact<<<NB, 256>>>(cnt, U);

    {
        cudaFuncSetAttribute(k_fused, cudaFuncAttributeMaxDynamicSharedMemorySize, F_SMEM);
        k_fused<<<(M + 63) / 64, 256, F_SMEM>>>(vf, up_w1, up_b1, up_w2, up_b2,
                                                ca_w1, ca_w2, sa_conv, M);
    }
    k_bnp<<<1, 256>>>(bn1_g, bn1_b, 256, 1.f / (float)M, 0);

    {
        cudaFuncSetAttribute(k_gemm2_mma, cudaFuncAttributeMaxDynamicSharedMemorySize, G2_SMEM);
        k_gemm2_mma<<<(M + 127) / 128, 256, G2_SMEM>>>((float*)d_out, M);
    }
    k_bnp<<<1, 64>>>(bn2_g, bn2_b, 64, 1.f / (float)M, 1);
    k_final<<<(M * 64 + 255) / 256, 256>>>((float*)d_out, M * 64);
}

// round 13
// speedup vs baseline: 1.1347x; 1.1347x over previous
#include <cuda_runtime.h>
#include <cuda_bf16.h>
#include <cuda_fp16.h>
#include <math.h>
#include <stdint.h>

// ---------------- static scratch (allocation-free) ----------------
#define UMAX 200000
__device__ int   g_winner[UMAX * 8];
__device__ int   g_selrows[UMAX];
__device__ int   g_bsum[256];
__device__ __align__(16) __half g_flat_h[(size_t)UMAX * 512];
__device__ __align__(16) __half g_wt_h[256 * 512];
__device__ __align__(16) __half g_w2t_h[64 * 256];
__device__ __align__(16) __half g_z1h[(size_t)UMAX * 256];
__device__ __align__(16) float g_stats1[512];   // sum[256] | sumsq[256]
__device__ __align__(16) float g_stats2[128];   // sum[64]  | sumsq[64]

__device__ __forceinline__ uint32_t smem_u32(const void* p) {
    uint32_t a;
    asm("{ .reg .u64 t; cvta.to.shared.u64 t, %1; cvt.u32.u64 %0, t; }" : "=r"(a) : "l"(p));
    return a;
}

// ---------------- init + weight prep (merged) ----------------
__global__ void k_init(int nwin, const float* __restrict__ W1, const float* __restrict__ W2) {
    int i = blockIdx.x * blockDim.x + threadIdx.x;
    if (i < nwin) g_winner[i] = -1;
    if (i < 512)  g_stats1[i] = 0.f;
    if (i < 128)  g_stats2[i] = 0.f;
    if (i < 131072) {
        int n = i >> 9, k = i & 511;
        g_wt_h[i] = __float2half(W1[(size_t)k * 256 + n]);
    }
    if (i < 16384) {
        int n = i >> 8, k = i & 255;
        g_w2t_h[i] = __float2half(W2[(size_t)k * 64 + n]);
    }
}

// ---------------- scatter: last-write-wins via max voxel index ----------------
__global__ void k_scatter(const int* __restrict__ coords, const int* __restrict__ inv, int Nv) {
    int i = blockIdx.x * blockDim.x + threadIdx.x;
    if (i < Nv) {
        int z = coords[(size_t)i * 4 + 1];
        int u = inv[i];
        atomicMax(&g_winner[(size_t)u * 8 + z], i);
    }
}

// ---------------- compaction: count per 1024-block ----------------
__global__ void k_count(const int* __restrict__ cnt, int U) {
    __shared__ int s[256];
    int base = blockIdx.x * 1024;
    int c = 0;
    for (int t = threadIdx.x; t < 1024; t += 256) {
        int u = base + t;
        if (u < U && cnt[u] >= 2) c++;
    }
    s[threadIdx.x] = c;
    __syncthreads();
    for (int o = 128; o > 0; o >>= 1) {
        if (threadIdx.x < o) s[threadIdx.x] += s[threadIdx.x + o];
        __syncthreads();
    }
    if (threadIdx.x == 0) g_bsum[blockIdx.x] = s[0];
}

// ---------------- compaction: in-block scan + self-computed block prefix ----------------
__global__ void k_compact(const int* __restrict__ cnt, int U) {
    __shared__ int s[256];
    __shared__ int spre[256];
    __shared__ int s_off;
    int tid = threadIdx.x;

    // block prefix: sum of g_bsum[0..bid)
    {
        int acc = 0;
        for (int i = tid; i < blockIdx.x; i += 256) acc += g_bsum[i];
        spre[tid] = acc;
        __syncthreads();
        for (int o = 128; o > 0; o >>= 1) {
            if (tid < o) spre[tid] += spre[tid + o];
            __syncthreads();
        }
        if (tid == 0) s_off = spre[0];
        __syncthreads();
    }

    int base = blockIdx.x * 1024 + tid * 4;
    int flags[4]; int c = 0;
    for (int q = 0; q < 4; q++) {
        int u = base + q;
        flags[q] = (u < U && cnt[u] >= 2) ? 1 : 0;
        c += flags[q];
    }
    s[tid] = c;
    __syncthreads();
    for (int o = 1; o < 256; o <<= 1) {
        int v = (tid >= o) ? s[tid - o] : 0;
        __syncthreads();
        s[tid] += v;
        __syncthreads();
    }
    int off = s_off + s[tid] - c;
    for (int q = 0; q < 4; q++) {
        if (flags[q]) g_selrows[off++] = base + q;
    }
}

// ---------------- fused per-row (warp-per-row): slot MLP + CBAM + flatten ----------------
__global__ void __launch_bounds__(256)
k_rows2(const float* __restrict__ vf,
        const float* __restrict__ w1, const float* __restrict__ b1,
        const float* __restrict__ w2g, const float* __restrict__ b2,
        const float* __restrict__ caw1, const float* __restrict__ caw2,
        const float* __restrict__ saconv, int M)
{
    __shared__ float sw1[160], sb1[32], sb2[64];
    __shared__ float scw1[512], scw2[512], sconv[16];
    __shared__ float sfeatw[8][40];
    __shared__ __align__(16) float shidw[8][8][32];

    const unsigned FULL = 0xffffffffu;
    int tid  = threadIdx.x;
    int wid  = tid >> 5;
    int lane = tid & 31;

    for (int i = tid; i < 160; i += 256) sw1[i] = w1[i];
    if (tid < 32) sb1[tid] = b1[tid];
    if (tid < 64) sb2[tid] = b2[tid];
    for (int i = tid; i < 512; i += 256) scw1[i] = caw1[i];
    for (int i = tid; i < 512; i += 256) scw2[i] = caw2[i];
    if (tid < 14) sconv[tid] = saconv[tid];

    float w2a[32], w2b[32];
#pragma unroll
    for (int k = 0; k < 32; k++) {
        w2a[k] = w2g[k * 64 + lane];
        w2b[k] = w2g[k * 64 + lane + 32];
    }
    __syncthreads();

    for (int r = 0; r < 8; r++) {
        int j = blockIdx.x * 64 + wid * 8 + r;
        if (j >= M) break;
        int u = g_selrows[j];
        int wv = (lane < 8) ? g_winner[(size_t)u * 8 + lane] : -1;

#pragma unroll
        for (int q = 0; q < 2; q++) {
            int t = lane + q * 32;
            int valid = (t < 40);
            int zz = valid ? (t / 5) : 0;
            int f  = t - zz * 5;
            int w = __shfl_sync(FULL, wv, zz);
            if (valid) sfeatw[wid][t] = (w >= 0) ? vf[(size_t)w * 5 + f] : 0.f;
        }
        __syncwarp();

#pragma unroll
        for (int z = 0; z < 8; z++) {
            float a = sb1[lane];
#pragma unroll
            for (int f = 0; f < 5; f++) a += sfeatw[wid][z * 5 + f] * sw1[f * 32 + lane];
            shidw[wid][z][lane] = fmaxf(a, 0.f);
        }
        __syncwarp();

        float x0[8], x1[8];
#pragma unroll
        for (int z = 0; z < 8; z++) {
            float a0 = sb2[lane], a1 = sb2[lane + 32];
            const float* hz = &shidw[wid][z][0];
#pragma unroll
            for (int k4 = 0; k4 < 8; k4++) {
                float4 h = *(const float4*)(hz + k4 * 4);
                a0 += h.x * w2a[k4 * 4] + h.y * w2a[k4 * 4 + 1] + h.z * w2a[k4 * 4 + 2] + h.w * w2a[k4 * 4 + 3];
                a1 += h.x * w2b[k4 * 4] + h.y * w2b[k4 * 4 + 1] + h.z * w2b[k4 * 4 + 2] + h.w * w2b[k4 * 4 + 3];
            }
            x0[z] = a0; x1[z] = a1;
        }

        float m0 = 0.f, m1 = 0.f, q0 = -3.4e38f, q1 = -3.4e38f;
#pragma unroll
        for (int z = 0; z < 8; z++) {
            m0 += x0[z]; m1 += x1[z];
            q0 = fmaxf(q0, x0[z]); q1 = fmaxf(q1, x1[z]);
        }
        m0 *= 0.125f; m1 *= 0.125f;

        float s8[8];
#pragma unroll
        for (int r8 = 0; r8 < 8; r8++) {
            float pm = m0 * scw1[lane * 8 + r8] + m1 * scw1[(lane + 32) * 8 + r8];
            float px = q0 * scw1[lane * 8 + r8] + q1 * scw1[(lane + 32) * 8 + r8];
#pragma unroll
            for (int o = 16; o > 0; o >>= 1) {
                pm += __shfl_xor_sync(FULL, pm, o);
                px += __shfl_xor_sync(FULL, px, o);
            }
            s8[r8] = fmaxf(pm, 0.f) + fmaxf(px, 0.f);
        }

        float a0 = 0.f, a1 = 0.f;
#pragma unroll
        for (int r8 = 0; r8 < 8; r8++) {
            a0 += s8[r8] * scw2[r8 * 64 + lane];
            a1 += s8[r8] * scw2[r8 * 64 + lane + 32];
        }
        float ca0 = 1.f / (1.f + expf(-a0));
        float ca1 = 1.f / (1.f + expf(-a1));
#pragma unroll
        for (int z = 0; z < 8; z++) { x0[z] *= ca0; x1[z] *= ca1; }

        float szm[8], szx[8];
#pragma unroll
        for (int z = 0; z < 8; z++) {
            float s = x0[z] + x1[z];
            float m = fmaxf(x0[z], x1[z]);
#pragma unroll
            for (int o = 16; o > 0; o >>= 1) {
                s += __shfl_xor_sync(FULL, s, o);
                m = fmaxf(m, __shfl_xor_sync(FULL, m, o));
            }
            szm[z] = s * (1.f / 64.f);
            szx[z] = m;
        }

        float sav = 0.f;
        if (lane < 8) {
            float acc = 0.f;
#pragma unroll
            for (int t = 0; t < 7; t++) {
                int p = lane + t - 3;
                if (p >= 0 && p < 8) acc += szm[p] * sconv[t] + szx[p] * sconv[7 + t];
            }
            sav = 1.f / (1.f + expf(-acc));
        }
        float sa[8];
#pragma unroll
        for (int z = 0; z < 8; z++) sa[z] = __shfl_sync(FULL, sav, z);

        size_t base = (size_t)j * 512;
        uint32_t ph[4];
#pragma unroll
        for (int z2 = 0; z2 < 4; z2++) {
            __half2 h2 = __floats2half2_rn(x0[2 * z2] * sa[2 * z2], x0[2 * z2 + 1] * sa[2 * z2 + 1]);
            ph[z2] = *(uint32_t*)&h2;
        }
        *(uint4*)&g_flat_h[base + lane * 8] = *(uint4*)ph;
#pragma unroll
        for (int z2 = 0; z2 < 4; z2++) {
            __half2 h2 = __floats2half2_rn(x1[2 * z2] * sa[2 * z2], x1[2 * z2 + 1] * sa[2 * z2 + 1]);
            ph[z2] = *(uint32_t*)&h2;
        }
        *(uint4*)&g_flat_h[base + (lane + 32) * 8] = *(uint4*)ph;
        __syncwarp();
    }
}

// ---------------- common mma macros ----------------
#define LDSM4(R0, R1, R2, R3, ADDR) \
    asm volatile("ldmatrix.sync.aligned.m8n8.x4.shared.b16 {%0,%1,%2,%3}, [%4];" \
                 : "=r"(R0), "=r"(R1), "=r"(R2), "=r"(R3) : "r"(ADDR))

#define MMA16816F16(D, A, B) \
    asm volatile("mma.sync.aligned.m16n8k16.row.col.f32.f16.f16.f32 " \
                 "{%0,%1,%2,%3}, {%4,%5,%6,%7}, {%8,%9}, {%0,%1,%2,%3};" \
                 : "+f"((D)[0]), "+f"((D)[1]), "+f"((D)[2]), "+f"((D)[3]) \
                 : "r"((A)[0]), "r"((A)[1]), "r"((A)[2]), "r"((A)[3]), \
                   "r"((B)[0]), "r"((B)[1]))

__device__ __forceinline__ void cp16z(uint32_t saddr, const void* gaddr, uint32_t sz) {
    asm volatile("cp.async.cg.shared.global [%0], [%1], 16, %2;"
                 :: "r"(saddr), "l"(gaddr), "r"(sz));
}

// ---------------- GEMM1 (mma.sync fp16 single-pass, 128x128 tile) + fused bn1 stats ----------------
#define G1_PITCHB  144
#define G1_A_OFF   0
#define G1_B_OFF   18432
#define G1_STAGE   36864

__global__ void __launch_bounds__(256, 2)
k_gemm1_mma(int M) {
    extern __shared__ __align__(16) char dsm[];
    uint32_t sbase = smem_u32(dsm);
    const unsigned FULL = 0xffffffffu;

    int tid  = threadIdx.x;
    int lane = tid & 31;
    int wid  = tid >> 5;
    int wm = wid & 1;
    int wn = wid >> 1;
    int row0 = blockIdx.x * 128;
    int col0 = blockIdx.y * 128;

    int li_r  = tid >> 3;
    int li_c8 = tid & 7;

    float acc[4][4][4] = {};

    auto load_chunk = [&](int c) {
        uint32_t st = sbase + (uint32_t)(c & 1) * G1_STAGE;
#pragma unroll
        for (int it = 0; it < 4; it++) {
            int r = li_r + it * 32;
            int gr = row0 + r;
            uint32_t soff = (uint32_t)(r * G1_PITCHB + li_c8 * 16);
            size_t goff = (size_t)gr * 512 + c * 64 + li_c8 * 8;
            uint32_t sz = (gr < M) ? 16u : 0u;
            cp16z(st + G1_A_OFF + soff, g_flat_h + goff, sz);
            int n = col0 + r;
            size_t boff = (size_t)n * 512 + c * 64 + li_c8 * 8;
            cp16z(st + G1_B_OFF + soff, g_wt_h + boff, 16u);
        }
        asm volatile("cp.async.commit_group;");
    };

    load_chunk(0);

    uint32_t aRow  = (uint32_t)(wm * 64 + (lane & 15));
    uint32_t aColB = (uint32_t)((lane >> 4) * 16);
    uint32_t bRow  = (uint32_t)(wn * 32 + ((lane >> 4) & 1) * 8 + (lane & 7));
    uint32_t bColB = (uint32_t)(((lane >> 3) & 1) * 16);

    for (int c = 0; c < 8; c++) {
        if (c < 7) load_chunk(c + 1);
        if (c < 7) { asm volatile("cp.async.wait_group 1;"); }
        else       { asm volatile("cp.async.wait_group 0;"); }
        __syncthreads();

        uint32_t st = sbase + (uint32_t)(c & 1) * G1_STAGE;
#pragma unroll
        for (int kk = 0; kk < 4; kk++) {
            uint32_t kb = (uint32_t)(kk * 32);
            uint32_t ah[4][4];
#pragma unroll
            for (int mi = 0; mi < 4; mi++) {
                uint32_t ad = st + G1_A_OFF + (aRow + mi * 16) * G1_PITCHB + kb + aColB;
                LDSM4(ah[mi][0], ah[mi][1], ah[mi][2], ah[mi][3], ad);
            }
            uint32_t bh[4][2];
#pragma unroll
            for (int nh = 0; nh < 2; nh++) {
                uint32_t bd = st + G1_B_OFF + (bRow + nh * 16) * G1_PITCHB + kb + bColB;
                uint32_t t0, t1, t2, t3;
                LDSM4(t0, t1, t2, t3, bd);
                bh[nh * 2][0] = t0; bh[nh * 2][1] = t1;
                bh[nh * 2 + 1][0] = t2; bh[nh * 2 + 1][1] = t3;
            }
#pragma unroll
            for (int mi = 0; mi < 4; mi++) {
#pragma unroll
                for (int ni = 0; ni < 4; ni++) {
                    MMA16816F16(acc[mi][ni], ah[mi], bh[ni]);
                }
            }
        }
        __syncthreads();
    }

    // z1 stored as fp16
#pragma unroll
    for (int mi = 0; mi < 4; mi++) {
#pragma unroll
        for (int ni = 0; ni < 4; ni++) {
            int grow = row0 + wm * 64 + mi * 16 + (lane >> 2);
            int gcol = col0 + wn * 32 + ni * 8 + (lane & 3) * 2;
            if (grow < M) {
                __half2 h = __floats2half2_rn(acc[mi][ni][0], acc[mi][ni][1]);
                *(uint32_t*)(g_z1h + (size_t)grow * 256 + gcol) = *(uint32_t*)&h;
            }
            if (grow + 8 < M) {
                __half2 h = __floats2half2_rn(acc[mi][ni][2], acc[mi][ni][3]);
                *(uint32_t*)(g_z1h + (size_t)(grow + 8) * 256 + gcol) = *(uint32_t*)&h;
            }
        }
    }

#pragma unroll
    for (int ni = 0; ni < 4; ni++) {
#pragma unroll
        for (int jj = 0; jj < 2; jj++) {
            float s = 0.f, s2 = 0.f;
#pragma unroll
            for (int mi = 0; mi < 4; mi++) {
                float v0 = acc[mi][ni][jj], v1 = acc[mi][ni][jj + 2];
                s += v0 + v1; s2 += v0 * v0 + v1 * v1;
            }
#pragma unroll
            for (int o = 4; o <= 16; o <<= 1) {
                s  += __shfl_xor_sync(FULL, s, o);
                s2 += __shfl_xor_sync(FULL, s2, o);
            }
            if ((lane >> 2) == 0) {
                int col = col0 + wn * 32 + ni * 8 + (lane & 3) * 2 + jj;
                atomicAdd(&g_stats1[col], s);
                atomicAdd(&g_stats1[256 + col], s2);
            }
        }
    }
}

// ---------------- GEMM2 (mma.sync fp16 single-pass): bn1 params computed in-kernel ----------------
#define G2_PITCHB  144
#define G2_A_OFF   0
#define G2_B_OFF   18432
#define G2_SMEM    27648

__global__ void __launch_bounds__(256, 2)
k_gemm2_mma(float* __restrict__ out,
            const float* __restrict__ bn1g, const float* __restrict__ bn1b,
            float invM, int M) {
    extern __shared__ __align__(16) char dsm2[];
    uint32_t sbase = smem_u32(dsm2);
    __shared__ float ss[128];
    __shared__ float sbn_sc[256], sbn_sh[256];
    const unsigned FULL = 0xffffffffu;

    int tid  = threadIdx.x;
    int lane = tid & 31;
    int wid  = tid >> 5;
    int row0 = blockIdx.x * 128;

    if (tid < 128) ss[tid] = 0.f;
    {
        float mu  = g_stats1[tid] * invM;
        float var = g_stats1[256 + tid] * invM - mu * mu;
        float s = bn1g[tid] * rsqrtf(var + 0.001f);
        sbn_sc[tid] = s;
        sbn_sh[tid] = bn1b[tid] - mu * s;
    }

    float acc[8][4] = {};

    uint32_t aRow  = (uint32_t)(wid * 16 + (lane & 15));
    uint32_t aColB = (uint32_t)((lane >> 4) * 16);
    uint32_t bRowB = (uint32_t)(((lane >> 4) & 1) * 8 + (lane & 7));
    uint32_t bColB = (uint32_t)(((lane >> 3) & 1) * 16);

    for (int c = 0; c < 4; c++) {
        __syncthreads();
        // ---- A: load z1 fp16, bn1+relu in fp32 (smem params), back to fp16 smem ----
        {
            int f4 = tid & 3;
            int colb = f4 * 16;
#pragma unroll
            for (int half = 0; half < 2; half++) {
                int r = (tid >> 2) + half * 64;
                int gr = row0 + r;
                uint32_t hv[8] = {};
                if (gr < M) {
                    const uint4* src = (const uint4*)(g_z1h + (size_t)gr * 256 + c * 64 + colb);
                    *(uint4*)&hv[0] = src[0];
                    *(uint4*)&hv[4] = src[1];
                }
                uint32_t outp[8];
#pragma unroll
                for (int p = 0; p < 8; p++) {
                    __half2 h2 = *(__half2*)&hv[p];
                    float2 v = __half22float2(h2);
                    int col = c * 64 + colb + p * 2;
                    float y0 = (gr < M) ? fmaxf(v.x * sbn_sc[col] + sbn_sh[col], 0.f) : 0.f;
                    float y1 = (gr < M) ? fmaxf(v.y * sbn_sc[col + 1] + sbn_sh[col + 1], 0.f) : 0.f;
                    __half2 o = __floats2half2_rn(y0, y1);
                    outp[p] = *(uint32_t*)&o;
                }
                uint32_t off = (uint32_t)(r * G2_PITCHB + colb * 2);
                *(uint4*)(dsm2 + G2_A_OFF + off)      = *(uint4*)&outp[0];
                *(uint4*)(dsm2 + G2_A_OFF + off + 16) = *(uint4*)&outp[4];
            }
        }
        // ---- B: copy w2t chunk (64 n x 64 k fp16) ----
        {
            int n = tid >> 2;
            int kg = (tid & 3) * 16;
            const uint4* gh = (const uint4*)(g_w2t_h + (size_t)n * 256 + c * 64 + kg);
            uint32_t off = (uint32_t)(n * G2_PITCHB + kg * 2);
            *(uint4*)(dsm2 + G2_B_OFF + off)      = gh[0];
            *(uint4*)(dsm2 + G2_B_OFF + off + 16) = gh[1];
        }
        __syncthreads();

#pragma unroll
        for (int kk = 0; kk < 4; kk++) {
            uint32_t kb = (uint32_t)(kk * 32);
            uint32_t ah[4];
            {
                uint32_t ad = sbase + G2_A_OFF + aRow * G2_PITCHB + kb + aColB;
                LDSM4(ah[0], ah[1], ah[2], ah[3], ad);
            }
            uint32_t bh[8][2];
#pragma unroll
            for (int nh = 0; nh < 4; nh++) {
                uint32_t bd = sbase + G2_B_OFF + (nh * 16 + bRowB) * G2_PITCHB + kb + bColB;
                uint32_t t0, t1, t2, t3;
                LDSM4(t0, t1, t2, t3, bd);
                bh[nh * 2][0] = t0; bh[nh * 2][1] = t1;
                bh[nh * 2 + 1][0] = t2; bh[nh * 2 + 1][1] = t3;
            }
#pragma unroll
            for (int ni = 0; ni < 8; ni++) {
                MMA16816F16(acc[ni], ah, bh[ni]);
            }
        }
    }

    int grow = row0 + wid * 16 + (lane >> 2);
#pragma unroll
    for (int ni = 0; ni < 8; ni++) {
        int gcol = ni * 8 + (lane & 3) * 2;
        if (grow < M)
            *(float2*)(out + (size_t)grow * 64 + gcol) = make_float2(acc[ni][0], acc[ni][1]);
        if (grow + 8 < M)
            *(float2*)(out + (size_t)(grow + 8) * 64 + gcol) = make_float2(acc[ni][2], acc[ni][3]);
    }

#pragma unroll
    for (int ni = 0; ni < 8; ni++) {
#pragma unroll
        for (int jj = 0; jj < 2; jj++) {
            float s = acc[ni][jj] + acc[ni][jj + 2];
            float s2 = acc[ni][jj] * acc[ni][jj] + acc[ni][jj + 2] * acc[ni][jj + 2];
#pragma unroll
            for (int o = 4; o <= 16; o <<= 1) {
                s  += __shfl_xor_sync(FULL, s, o);
                s2 += __shfl_xor_sync(FULL, s2, o);
            }
            if ((lane >> 2) == 0) {
                int col = ni * 8 + (lane & 3) * 2 + jj;
                atomicAdd(&ss[col], s);
                atomicAdd(&ss[64 + col], s2);
            }
        }
    }
    __syncthreads();
    if (tid < 128) atomicAdd(&g_stats2[tid], ss[tid]);
}

// ---------------- final: bn2 params computed in-kernel + normalize ----------------
__global__ void k_final(float* __restrict__ out,
                        const float* __restrict__ bn2g, const float* __restrict__ bn2b,
                        float invM, int n) {
    __shared__ float sc[64], sh[64];
    if (threadIdx.x < 64) {
        int c = threadIdx.x;
        float mu  = g_stats2[c] * invM;
        float var = g_stats2[64 + c] * invM - mu * mu;
        float s = bn2g[c] * rsqrtf(var + 0.001f);
        sc[c] = s;
        sh[c] = bn2b[c] - mu * s;
    }
    __syncthreads();
    int i = blockIdx.x * blockDim.x + threadIdx.x;
    if (i < n) {
        int c = i & 63;
        out[i] = fmaxf(out[i] * sc[c] + sh[c], 0.f);
    }
}

// ---------------- launcher ----------------
extern "C" void kernel_launch(void* const* d_in, const int* in_sizes, int n_in,
                              void* d_out, int out_size) {
    const float* vf      = (const float*)d_in[0];
    const int*   coords  = (const int*)d_in[1];
    const int*   inv     = (const int*)d_in[3];
    const int*   cnt     = (const int*)d_in[4];
    const float* up_w1   = (const float*)d_in[5];
    const float* up_b1   = (const float*)d_in[6];
    const float* up_w2   = (const float*)d_in[7];
    const float* up_b2   = (const float*)d_in[8];
    const float* ca_w1   = (const float*)d_in[9];
    const float* ca_w2   = (const float*)d_in[10];
    const float* sa_conv = (const float*)d_in[11];
    const float* bs_w1   = (const float*)d_in[12];
    const float* bn1_g   = (const float*)d_in[13];
    const float* bn1_b   = (const float*)d_in[14];
    const float* bs_w2   = (const float*)d_in[15];
    const float* bn2_g   = (const float*)d_in[16];
    const float* bn2_b   = (const float*)d_in[17];

    int Nv = in_sizes[0] / 5;
    int U  = in_sizes[2];
    int M  = out_size / 64;
    if (M <= 0) return;

    int nwin = U * 8;
    k_init<<<(nwin + 255) / 256, 256>>>(nwin, bs_w1, bs_w2);
    k_scatter<<<(Nv + 255) / 256, 256>>>(coords, inv, Nv);

    int NB = (U + 1023) / 1024;
    k_count<<<NB, 256>>>(cnt, U);
    k_compact<<<NB, 256>>>(cnt, U);

    k_rows2<<<(M + 63) / 64, 256>>>(vf, up_w1, up_b1, up_w2, up_b2,
                                    ca_w1, ca_w2, sa_conv, M);

    {
        int dynsmem = 2 * G1_STAGE;
        cudaFuncSetAttribute(k_gemm1_mma, cudaFuncAttributeMaxDynamicSharedMemorySize, dynsmem);
        dim3 g1((M + 127) / 128, 2);
        k_gemm1_mma<<<g1, 256, dynsmem>>>(M);
    }

    {
        cudaFuncSetAttribute(k_gemm2_mma, cudaFuncAttributeMaxDynamicSharedMemorySize, G2_SMEM);
        k_gemm2_mma<<<(M + 127) / 128, 256, G2_SMEM>>>((float*)d_out, bn1_g, bn1_b,
                                                       1.f / (float)M, M);
    }
    k_final<<<(M * 64 + 255) / 256, 256>>>((float*)d_out, bn2_g, bn2_b,
                                           1.f / (float)M, M * 64);
}

// round 14
// speedup vs baseline: 1.2333x; 1.0869x over previous
#include <cuda_runtime.h>
#include <cuda_bf16.h>
#include <cuda_fp16.h>
#include <math.h>
#include <stdint.h>

// ---------------- static scratch (allocation-free) ----------------
#define UMAX 200000
__device__ int   g_winner[UMAX * 8];
__device__ int   g_selrows[UMAX];
__device__ int   g_bsum[256];
__device__ __align__(16) __half g_flat_h[(size_t)UMAX * 512];
__device__ __align__(16) __half g_wt_h[256 * 512];
__device__ __align__(16) __half g_w2t_h[64 * 256];
__device__ __align__(16) __half g_z1h[(size_t)UMAX * 256];
__device__ __align__(16) float g_stats1[512];   // sum[256] | sumsq[256]
__device__ __align__(16) float g_stats2[128];   // sum[64]  | sumsq[64]

__device__ __forceinline__ uint32_t smem_u32(const void* p) {
    uint32_t a;
    asm("{ .reg .u64 t; cvta.to.shared.u64 t, %1; cvt.u32.u64 %0, t; }" : "=r"(a) : "l"(p));
    return a;
}

// ---------------- init + weight prep (merged) ----------------
__global__ void k_init(int nwin, const float* __restrict__ W1, const float* __restrict__ W2) {
    int i = blockIdx.x * blockDim.x + threadIdx.x;
    if (i < nwin) g_winner[i] = -1;
    if (i < 512)  g_stats1[i] = 0.f;
    if (i < 128)  g_stats2[i] = 0.f;
    if (i < 131072) {
        int n = i >> 9, k = i & 511;
        g_wt_h[i] = __float2half(W1[(size_t)k * 256 + n]);
    }
    if (i < 16384) {
        int n = i >> 8, k = i & 255;
        g_w2t_h[i] = __float2half(W2[(size_t)k * 64 + n]);
    }
}

// ---------------- scatter: last-write-wins via max voxel index ----------------
__global__ void k_scatter(const int* __restrict__ coords, const int* __restrict__ inv, int Nv) {
    int i = blockIdx.x * blockDim.x + threadIdx.x;
    if (i < Nv) {
        int z = coords[(size_t)i * 4 + 1];
        int u = inv[i];
        atomicMax(&g_winner[(size_t)u * 8 + z], i);
    }
}

// ---------------- compaction: count per 1024-block ----------------
__global__ void k_count(const int* __restrict__ cnt, int U) {
    __shared__ int s[256];
    int base = blockIdx.x * 1024;
    int c = 0;
    for (int t = threadIdx.x; t < 1024; t += 256) {
        int u = base + t;
        if (u < U && cnt[u] >= 2) c++;
    }
    s[threadIdx.x] = c;
    __syncthreads();
    for (int o = 128; o > 0; o >>= 1) {
        if (threadIdx.x < o) s[threadIdx.x] += s[threadIdx.x + o];
        __syncthreads();
    }
    if (threadIdx.x == 0) g_bsum[blockIdx.x] = s[0];
}

// ---------------- compaction: in-block scan + self-computed block prefix ----------------
__global__ void k_compact(const int* __restrict__ cnt, int U) {
    __shared__ int s[256];
    __shared__ int spre[256];
    __shared__ int s_off;
    int tid = threadIdx.x;
    {
        int acc = 0;
        for (int i = tid; i < blockIdx.x; i += 256) acc += g_bsum[i];
        spre[tid] = acc;
        __syncthreads();
        for (int o = 128; o > 0; o >>= 1) {
            if (tid < o) spre[tid] += spre[tid + o];
            __syncthreads();
        }
        if (tid == 0) s_off = spre[0];
        __syncthreads();
    }
    int base = blockIdx.x * 1024 + tid * 4;
    int flags[4]; int c = 0;
    for (int q = 0; q < 4; q++) {
        int u = base + q;
        flags[q] = (u < U && cnt[u] >= 2) ? 1 : 0;
        c += flags[q];
    }
    s[tid] = c;
    __syncthreads();
    for (int o = 1; o < 256; o <<= 1) {
        int v = (tid >= o) ? s[tid - o] : 0;
        __syncthreads();
        s[tid] += v;
        __syncthreads();
    }
    int off = s_off + s[tid] - c;
    for (int q = 0; q < 4; q++) {
        if (flags[q]) g_selrows[off++] = base + q;
    }
}

// ---------------- common mma macros ----------------
#define LDSM4(R0, R1, R2, R3, ADDR) \
    asm volatile("ldmatrix.sync.aligned.m8n8.x4.shared.b16 {%0,%1,%2,%3}, [%4];" \
                 : "=r"(R0), "=r"(R1), "=r"(R2), "=r"(R3) : "r"(ADDR))

#define MMA16816F16(D, A, B) \
    asm volatile("mma.sync.aligned.m16n8k16.row.col.f32.f16.f16.f32 " \
                 "{%0,%1,%2,%3}, {%4,%5,%6,%7}, {%8,%9}, {%0,%1,%2,%3};" \
                 : "+f"((D)[0]), "+f"((D)[1]), "+f"((D)[2]), "+f"((D)[3]) \
                 : "r"((A)[0]), "r"((A)[1]), "r"((A)[2]), "r"((A)[3]), \
                   "r"((B)[0]), "r"((B)[1]))

__device__ __forceinline__ void cp16z(uint32_t saddr, const void* gaddr, uint32_t sz) {
    asm volatile("cp.async.cg.shared.global [%0], [%1], 16, %2;"
                 :: "r"(saddr), "l"(gaddr), "r"(sz));
}

// ---------------- k_rows2: slot MLP (tensorized hi/lo) + CBAM + flatten ----------------
// smem layout (bytes):
//   W2H 0 (64x80), W2L 5120 (64x80)
//   per-warp @10240 + wid*7488: HIDH +0 (16x80), HIDL +1280, XBUF +2560 (16x72 f32), FEAT +7168 (80 f32)
//   BC floats @70144: sw1 0(160) sb1 160(32) sb2 192(64) scw1 256(512) scw2 768(512) sconv 1280(14)
#define R_W2H   0
#define R_W2L   5120
#define R_WARP0 10240
#define R_WSTR  7488
#define R_HIDH  0
#define R_HIDL  1280
#define R_XBUF  2560
#define R_FEAT  7168
#define R_BC    70144
#define R_SMEM  75328

__global__ void __launch_bounds__(256, 2)
k_rows2(const float* __restrict__ vf,
        const float* __restrict__ w1, const float* __restrict__ b1,
        const float* __restrict__ w2g, const float* __restrict__ b2,
        const float* __restrict__ caw1, const float* __restrict__ caw2,
        const float* __restrict__ saconv, int M)
{
    extern __shared__ __align__(16) char dsm[];
    uint32_t sbase = smem_u32(dsm);
    float* bc = (float*)(dsm + R_BC);
    float* sw1f  = bc + 0;
    float* sb1f  = bc + 160;
    float* sb2f  = bc + 192;
    float* scw1f = bc + 256;
    float* scw2f = bc + 768;
    float* sconvf = bc + 1280;

    const unsigned FULL = 0xffffffffu;
    int tid  = threadIdx.x;
    int wid  = tid >> 5;
    int lane = tid & 31;
    int row0 = blockIdx.x * 64;

    // broadcast weights
    for (int i = tid; i < 160; i += 256) sw1f[i] = w1[i];
    if (tid < 32) sb1f[tid] = b1[tid];
    if (tid < 64) sb2f[tid] = b2[tid];
    for (int i = tid; i < 512; i += 256) scw1f[i] = caw1[i];
    for (int i = tid; i < 512; i += 256) scw2f[i] = caw2[i];
    if (tid < 14) sconvf[tid] = saconv[tid];

    // w2 tile -> smem [n=64][k=32] fp16 hi/lo, pitch 80B
    for (int i = tid; i < 2048; i += 256) {
        int n = i >> 5, k = i & 31;
        float w = w2g[k * 64 + n];
        __half hh = __float2half(w);
        float lo = w - __half2float(hh);
        *(__half*)(dsm + R_W2H + n * 80 + k * 2) = hh;
        *(__half*)(dsm + R_W2L + n * 80 + k * 2) = __float2half(lo);
    }
    __syncthreads();

    uint32_t wbase = sbase + R_WARP0 + (uint32_t)wid * R_WSTR;
    float* featp = (float*)(dsm + R_WARP0 + wid * R_WSTR + R_FEAT);
    float* xb    = (float*)(dsm + R_WARP0 + wid * R_WSTR + R_XBUF);
    __half* hidh = (__half*)(dsm + R_WARP0 + wid * R_WSTR + R_HIDH);
    __half* hidl = (__half*)(dsm + R_WARP0 + wid * R_WSTR + R_HIDL);

    uint32_t aColB = (uint32_t)((lane >> 4) * 16);
    uint32_t aRowO = (uint32_t)((lane & 15) * 80);
    uint32_t bRowB = (uint32_t)(((lane >> 4) & 1) * 8 + (lane & 7));
    uint32_t bColB = (uint32_t)(((lane >> 3) & 1) * 16);

    for (int rp = 0; rp < 4; rp++) {
        int j0 = row0 + wid * 8 + rp * 2;
        if (j0 >= M) break;

        // gather features for 2 rows (16 slots)
#pragma unroll
        for (int rr = 0; rr < 2; rr++) {
            int j = j0 + rr;
            int valid = (j < M);
            int u = valid ? g_selrows[j] : 0;
            int wv = (valid && lane < 8) ? g_winner[(size_t)u * 8 + lane] : -1;
#pragma unroll
            for (int q = 0; q < 2; q++) {
                int t = lane + q * 32;
                int tv = (t < 40);
                int zz = tv ? (t / 5) : 0;
                int f  = t - zz * 5;
                int w = __shfl_sync(FULL, wv, zz);
                if (tv) featp[rr * 40 + t] = (w >= 0) ? vf[(size_t)w * 5 + f] : 0.f;
            }
        }
        __syncwarp();

        // hidden layer: 16 slots, lane = hidden unit; write fp16 hi/lo to smem
#pragma unroll
        for (int z = 0; z < 16; z++) {
            const float* ft = featp + (z >> 3) * 40 + (z & 7) * 5;
            float a = sb1f[lane];
#pragma unroll
            for (int f = 0; f < 5; f++) a += ft[f] * sw1f[f * 32 + lane];
            a = fmaxf(a, 0.f);
            __half hh = __float2half(a);
            float lo = a - __half2float(hh);
            hidh[z * 40 + lane] = hh;
            hidl[z * 40 + lane] = __float2half(lo);
        }
        __syncwarp();

        // MMA: x[16 slots][64 ch] = hid @ w2 (3-pass hi/lo)
        float acc[8][4] = {};
#pragma unroll
        for (int kk = 0; kk < 2; kk++) {
            uint32_t kb = (uint32_t)(kk * 32);
            uint32_t ah[4], al[4];
            LDSM4(ah[0], ah[1], ah[2], ah[3], wbase + R_HIDH + aRowO + kb + aColB);
            LDSM4(al[0], al[1], al[2], al[3], wbase + R_HIDL + aRowO + kb + aColB);
            uint32_t bh[8][2], bl[8][2];
#pragma unroll
            for (int nh = 0; nh < 4; nh++) {
                uint32_t rofs = (uint32_t)(nh * 16 + bRowB) * 80 + kb + bColB;
                uint32_t t0, t1, t2, t3;
                LDSM4(t0, t1, t2, t3, sbase + R_W2H + rofs);
                bh[nh * 2][0] = t0; bh[nh * 2][1] = t1;
                bh[nh * 2 + 1][0] = t2; bh[nh * 2 + 1][1] = t3;
                LDSM4(t0, t1, t2, t3, sbase + R_W2L + rofs);
                bl[nh * 2][0] = t0; bl[nh * 2][1] = t1;
                bl[nh * 2 + 1][0] = t2; bl[nh * 2 + 1][1] = t3;
            }
#pragma unroll
            for (int ni = 0; ni < 8; ni++) {
                MMA16816F16(acc[ni], ah, bh[ni]);
                MMA16816F16(acc[ni], ah, bl[ni]);
                MMA16816F16(acc[ni], al, bh[ni]);
            }
        }

        // store acc -> xbuf [slot][ch], pitch 72 floats (conflict-free)
        {
            int r0 = lane >> 2, c0 = (lane & 3) * 2;
#pragma unroll
            for (int ni = 0; ni < 8; ni++) {
                *(float2*)&xb[r0 * 72 + ni * 8 + c0]       = make_float2(acc[ni][0], acc[ni][1]);
                *(float2*)&xb[(r0 + 8) * 72 + ni * 8 + c0] = make_float2(acc[ni][2], acc[ni][3]);
            }
        }
        __syncwarp();

        // per-row CBAM (x from xbuf + bias)
#pragma unroll
        for (int rr = 0; rr < 2; rr++) {
            int j = j0 + rr;
            float x0[8], x1[8];
#pragma unroll
            for (int z = 0; z < 8; z++) {
                x0[z] = xb[(rr * 8 + z) * 72 + lane]      + sb2f[lane];
                x1[z] = xb[(rr * 8 + z) * 72 + lane + 32] + sb2f[lane + 32];
            }

            float m0 = 0.f, m1 = 0.f, q0 = -3.4e38f, q1 = -3.4e38f;
#pragma unroll
            for (int z = 0; z < 8; z++) {
                m0 += x0[z]; m1 += x1[z];
                q0 = fmaxf(q0, x0[z]); q1 = fmaxf(q1, x1[z]);
            }
            m0 *= 0.125f; m1 *= 0.125f;

            float s8[8];
#pragma unroll
            for (int r8 = 0; r8 < 8; r8++) {
                float pm = m0 * scw1f[lane * 8 + r8] + m1 * scw1f[(lane + 32) * 8 + r8];
                float px = q0 * scw1f[lane * 8 + r8] + q1 * scw1f[(lane + 32) * 8 + r8];
#pragma unroll
                for (int o = 16; o > 0; o >>= 1) {
                    pm += __shfl_xor_sync(FULL, pm, o);
                    px += __shfl_xor_sync(FULL, px, o);
                }
                s8[r8] = fmaxf(pm, 0.f) + fmaxf(px, 0.f);
            }

            float a0 = 0.f, a1 = 0.f;
#pragma unroll
            for (int r8 = 0; r8 < 8; r8++) {
                a0 += s8[r8] * scw2f[r8 * 64 + lane];
                a1 += s8[r8] * scw2f[r8 * 64 + lane + 32];
            }
            float ca0 = 1.f / (1.f + expf(-a0));
            float ca1 = 1.f / (1.f + expf(-a1));
#pragma unroll
            for (int z = 0; z < 8; z++) { x0[z] *= ca0; x1[z] *= ca1; }

            float szm[8], szx[8];
#pragma unroll
            for (int z = 0; z < 8; z++) {
                float s = x0[z] + x1[z];
                float m = fmaxf(x0[z], x1[z]);
#pragma unroll
                for (int o = 16; o > 0; o >>= 1) {
                    s += __shfl_xor_sync(FULL, s, o);
                    m = fmaxf(m, __shfl_xor_sync(FULL, m, o));
                }
                szm[z] = s * (1.f / 64.f);
                szx[z] = m;
            }

            float sav = 0.f;
            if (lane < 8) {
                float acc2 = 0.f;
#pragma unroll
                for (int t = 0; t < 7; t++) {
                    int p = lane + t - 3;
                    if (p >= 0 && p < 8) acc2 += szm[p] * sconvf[t] + szx[p] * sconvf[7 + t];
                }
                sav = 1.f / (1.f + expf(-acc2));
            }
            float sa[8];
#pragma unroll
            for (int z = 0; z < 8; z++) sa[z] = __shfl_sync(FULL, sav, z);

            if (j < M) {
                size_t base = (size_t)j * 512;
                uint32_t ph[4];
#pragma unroll
                for (int z2 = 0; z2 < 4; z2++) {
                    __half2 h2 = __floats2half2_rn(x0[2 * z2] * sa[2 * z2], x0[2 * z2 + 1] * sa[2 * z2 + 1]);
                    ph[z2] = *(uint32_t*)&h2;
                }
                *(uint4*)&g_flat_h[base + lane * 8] = *(uint4*)ph;
#pragma unroll
                for (int z2 = 0; z2 < 4; z2++) {
                    __half2 h2 = __floats2half2_rn(x1[2 * z2] * sa[2 * z2], x1[2 * z2 + 1] * sa[2 * z2 + 1]);
                    ph[z2] = *(uint32_t*)&h2;
                }
                *(uint4*)&g_flat_h[base + (lane + 32) * 8] = *(uint4*)ph;
            }
        }
        __syncwarp();
    }
}

// ---------------- GEMM1 (mma.sync fp16 single-pass, 128x128 tile) + fused bn1 stats ----------------
#define G1_PITCHB  144
#define G1_A_OFF   0
#define G1_B_OFF   18432
#define G1_STAGE   36864

__global__ void __launch_bounds__(256, 2)
k_gemm1_mma(int M) {
    extern __shared__ __align__(16) char dsm[];
    uint32_t sbase = smem_u32(dsm);
    const unsigned FULL = 0xffffffffu;

    int tid  = threadIdx.x;
    int lane = tid & 31;
    int wid  = tid >> 5;
    int wm = wid & 1;
    int wn = wid >> 1;
    int row0 = blockIdx.x * 128;
    int col0 = blockIdx.y * 128;

    int li_r  = tid >> 3;
    int li_c8 = tid & 7;

    float acc[4][4][4] = {};

    auto load_chunk = [&](int c) {
        uint32_t st = sbase + (uint32_t)(c & 1) * G1_STAGE;
#pragma unroll
        for (int it = 0; it < 4; it++) {
            int r = li_r + it * 32;
            int gr = row0 + r;
            uint32_t soff = (uint32_t)(r * G1_PITCHB + li_c8 * 16);
            size_t goff = (size_t)gr * 512 + c * 64 + li_c8 * 8;
            uint32_t sz = (gr < M) ? 16u : 0u;
            cp16z(st + G1_A_OFF + soff, g_flat_h + goff, sz);
            int n = col0 + r;
            size_t boff = (size_t)n * 512 + c * 64 + li_c8 * 8;
            cp16z(st + G1_B_OFF + soff, g_wt_h + boff, 16u);
        }
        asm volatile("cp.async.commit_group;");
    };

    load_chunk(0);

    uint32_t aRow  = (uint32_t)(wm * 64 + (lane & 15));
    uint32_t aColB = (uint32_t)((lane >> 4) * 16);
    uint32_t bRow  = (uint32_t)(wn * 32 + ((lane >> 4) & 1) * 8 + (lane & 7));
    uint32_t bColB = (uint32_t)(((lane >> 3) & 1) * 16);

    for (int c = 0; c < 8; c++) {
        if (c < 7) load_chunk(c + 1);
        if (c < 7) { asm volatile("cp.async.wait_group 1;"); }
        else       { asm volatile("cp.async.wait_group 0;"); }
        __syncthreads();

        uint32_t st = sbase + (uint32_t)(c & 1) * G1_STAGE;
#pragma unroll
        for (int kk = 0; kk < 4; kk++) {
            uint32_t kb = (uint32_t)(kk * 32);
            uint32_t ah[4][4];
#pragma unroll
            for (int mi = 0; mi < 4; mi++) {
                uint32_t ad = st + G1_A_OFF + (aRow + mi * 16) * G1_PITCHB + kb + aColB;
                LDSM4(ah[mi][0], ah[mi][1], ah[mi][2], ah[mi][3], ad);
            }
            uint32_t bh[4][2];
#pragma unroll
            for (int nh = 0; nh < 2; nh++) {
                uint32_t bd = st + G1_B_OFF + (bRow + nh * 16) * G1_PITCHB + kb + bColB;
                uint32_t t0, t1, t2, t3;
                LDSM4(t0, t1, t2, t3, bd);
                bh[nh * 2][0] = t0; bh[nh * 2][1] = t1;
                bh[nh * 2 + 1][0] = t2; bh[nh * 2 + 1][1] = t3;
            }
#pragma unroll
            for (int mi = 0; mi < 4; mi++) {
#pragma unroll
                for (int ni = 0; ni < 4; ni++) {
                    MMA16816F16(acc[mi][ni], ah[mi], bh[ni]);
                }
            }
        }
        __syncthreads();
    }

#pragma unroll
    for (int mi = 0; mi < 4; mi++) {
#pragma unroll
        for (int ni = 0; ni < 4; ni++) {
            int grow = row0 + wm * 64 + mi * 16 + (lane >> 2);
            int gcol = col0 + wn * 32 + ni * 8 + (lane & 3) * 2;
            if (grow < M) {
                __half2 h = __floats2half2_rn(acc[mi][ni][0], acc[mi][ni][1]);
                *(uint32_t*)(g_z1h + (size_t)grow * 256 + gcol) = *(uint32_t*)&h;
            }
            if (grow + 8 < M) {
                __half2 h = __floats2half2_rn(acc[mi][ni][2], acc[mi][ni][3]);
                *(uint32_t*)(g_z1h + (size_t)(grow + 8) * 256 + gcol) = *(uint32_t*)&h;
            }
        }
    }

#pragma unroll
    for (int ni = 0; ni < 4; ni++) {
#pragma unroll
        for (int jj = 0; jj < 2; jj++) {
            float s = 0.f, s2 = 0.f;
#pragma unroll
            for (int mi = 0; mi < 4; mi++) {
                float v0 = acc[mi][ni][jj], v1 = acc[mi][ni][jj + 2];
                s += v0 + v1; s2 += v0 * v0 + v1 * v1;
            }
#pragma unroll
            for (int o = 4; o <= 16; o <<= 1) {
                s  += __shfl_xor_sync(FULL, s, o);
                s2 += __shfl_xor_sync(FULL, s2, o);
            }
            if ((lane >> 2) == 0) {
                int col = col0 + wn * 32 + ni * 8 + (lane & 3) * 2 + jj;
                atomicAdd(&g_stats1[col], s);
                atomicAdd(&g_stats1[256 + col], s2);
            }
        }
    }
}

// ---------------- GEMM2 (mma.sync fp16 single-pass): bn1 params computed in-kernel ----------------
#define G2_PITCHB  144
#define G2_A_OFF   0
#define G2_B_OFF   18432
#define G2_SMEM    27648

__global__ void __launch_bounds__(256, 2)
k_gemm2_mma(float* __restrict__ out,
            const float* __restrict__ bn1g, const float* __restrict__ bn1b,
            float invM, int M) {
    extern __shared__ __align__(16) char dsm2[];
    uint32_t sbase = smem_u32(dsm2);
    __shared__ float ss[128];
    __shared__ float sbn_sc[256], sbn_sh[256];
    const unsigned FULL = 0xffffffffu;

    int tid  = threadIdx.x;
    int lane = tid & 31;
    int wid  = tid >> 5;
    int row0 = blockIdx.x * 128;

    if (tid < 128) ss[tid] = 0.f;
    {
        float mu  = g_stats1[tid] * invM;
        float var = g_stats1[256 + tid] * invM - mu * mu;
        float s = bn1g[tid] * rsqrtf(var + 0.001f);
        sbn_sc[tid] = s;
        sbn_sh[tid] = bn1b[tid] - mu * s;
    }

    float acc[8][4] = {};

    uint32_t aRow  = (uint32_t)(wid * 16 + (lane & 15));
    uint32_t aColB = (uint32_t)((lane >> 4) * 16);
    uint32_t bRowB = (uint32_t)(((lane >> 4) & 1) * 8 + (lane & 7));
    uint32_t bColB = (uint32_t)(((lane >> 3) & 1) * 16);

    for (int c = 0; c < 4; c++) {
        __syncthreads();
        {
            int f4 = tid & 3;
            int colb = f4 * 16;
#pragma unroll
            for (int half = 0; half < 2; half++) {
                int r = (tid >> 2) + half * 64;
                int gr = row0 + r;
                uint32_t hv[8] = {};
                if (gr < M) {
                    const uint4* src = (const uint4*)(g_z1h + (size_t)gr * 256 + c * 64 + colb);
                    *(uint4*)&hv[0] = src[0];
                    *(uint4*)&hv[4] = src[1];
                }
                uint32_t outp[8];
#pragma unroll
                for (int p = 0; p < 8; p++) {
                    __half2 h2 = *(__half2*)&hv[p];
                    float2 v = __half22float2(h2);
                    int col = c * 64 + colb + p * 2;
                    float y0 = (gr < M) ? fmaxf(v.x * sbn_sc[col] + sbn_sh[col], 0.f) : 0.f;
                    float y1 = (gr < M) ? fmaxf(v.y * sbn_sc[col + 1] + sbn_sh[col + 1], 0.f) : 0.f;
                    __half2 o = __floats2half2_rn(y0, y1);
                    outp[p] = *(uint32_t*)&o;
                }
                uint32_t off = (uint32_t)(r * G2_PITCHB + colb * 2);
                *(uint4*)(dsm2 + G2_A_OFF + off)      = *(uint4*)&outp[0];
                *(uint4*)(dsm2 + G2_A_OFF + off + 16) = *(uint4*)&outp[4];
            }
        }
        {
            int n = tid >> 2;
            int kg = (tid & 3) * 16;
            const uint4* gh = (const uint4*)(g_w2t_h + (size_t)n * 256 + c * 64 + kg);
            uint32_t off = (uint32_t)(n * G2_PITCHB + kg * 2);
            *(uint4*)(dsm2 + G2_B_OFF + off)      = gh[0];
            *(uint4*)(dsm2 + G2_B_OFF + off + 16) = gh[1];
        }
        __syncthreads();

#pragma unroll
        for (int kk = 0; kk < 4; kk++) {
            uint32_t kb = (uint32_t)(kk * 32);
            uint32_t ah[4];
            {
                uint32_t ad = sbase + G2_A_OFF + aRow * G2_PITCHB + kb + aColB;
                LDSM4(ah[0], ah[1], ah[2], ah[3], ad);
            }
            uint32_t bh[8][2];
#pragma unroll
            for (int nh = 0; nh < 4; nh++) {
                uint32_t bd = sbase + G2_B_OFF + (nh * 16 + bRowB) * G2_PITCHB + kb + bColB;
                uint32_t t0, t1, t2, t3;
                LDSM4(t0, t1, t2, t3, bd);
                bh[nh * 2][0] = t0; bh[nh * 2][1] = t1;
                bh[nh * 2 + 1][0] = t2; bh[nh * 2 + 1][1] = t3;
            }
#pragma unroll
            for (int ni = 0; ni < 8; ni++) {
                MMA16816F16(acc[ni], ah, bh[ni]);
            }
        }
    }

    int grow = row0 + wid * 16 + (lane >> 2);
#pragma unroll
    for (int ni = 0; ni < 8; ni++) {
        int gcol = ni * 8 + (lane & 3) * 2;
        if (grow < M)
            *(float2*)(out + (size_t)grow * 64 + gcol) = make_float2(acc[ni][0], acc[ni][1]);
        if (grow + 8 < M)
            *(float2*)(out + (size_t)(grow + 8) * 64 + gcol) = make_float2(acc[ni][2], acc[ni][3]);
    }

#pragma unroll
    for (int ni = 0; ni < 8; ni++) {
#pragma unroll
        for (int jj = 0; jj < 2; jj++) {
            float s = acc[ni][jj] + acc[ni][jj + 2];
            float s2 = acc[ni][jj] * acc[ni][jj] + acc[ni][jj + 2] * acc[ni][jj + 2];
#pragma unroll
            for (int o = 4; o <= 16; o <<= 1) {
                s  += __shfl_xor_sync(FULL, s, o);
                s2 += __shfl_xor_sync(FULL, s2, o);
            }
            if ((lane >> 2) == 0) {
                int col = ni * 8 + (lane & 3) * 2 + jj;
                atomicAdd(&ss[col], s);
                atomicAdd(&ss[64 + col], s2);
            }
        }
    }
    __syncthreads();
    if (tid < 128) atomicAdd(&g_stats2[tid], ss[tid]);
}

// ---------------- final: bn2 params computed in-kernel + normalize ----------------
__global__ void k_final(float* __restrict__ out,
                        const float* __restrict__ bn2g, const float* __restrict__ bn2b,
                        float invM, int n) {
    __shared__ float sc[64], sh[64];
    if (threadIdx.x < 64) {
        int c = threadIdx.x;
        float mu  = g_stats2[c] * invM;
        float var = g_stats2[64 + c] * invM - mu * mu;
        float s = bn2g[c] * rsqrtf(var + 0.001f);
        sc[c] = s;
        sh[c] = bn2b[c] - mu * s;
    }
    __syncthreads();
    int i = blockIdx.x * blockDim.x + threadIdx.x;
    if (i < n) {
        int c = i & 63;
        out[i] = fmaxf(out[i] * sc[c] + sh[c], 0.f);
    }
}

// ---------------- launcher ----------------
extern "C" void kernel_launch(void* const* d_in, const int* in_sizes, int n_in,
                              void* d_out, int out_size) {
    const float* vf      = (const float*)d_in[0];
    const int*   coords  = (const int*)d_in[1];
    const int*   inv     = (const int*)d_in[3];
    const int*   cnt     = (const int*)d_in[4];
    const float* up_w1   = (const float*)d_in[5];
    const float* up_b1   = (const float*)d_in[6];
    const float* up_w2   = (const float*)d_in[7];
    const float* up_b2   = (const float*)d_in[8];
    const float* ca_w1   = (const float*)d_in[9];
    const float* ca_w2   = (const float*)d_in[10];
    const float* sa_conv = (const float*)d_in[11];
    const float* bs_w1   = (const float*)d_in[12];
    const float* bn1_g   = (const float*)d_in[13];
    const float* bn1_b   = (const float*)d_in[14];
    const float* bs_w2   = (const float*)d_in[15];
    const float* bn2_g   = (const float*)d_in[16];
    const float* bn2_b   = (const float*)d_in[17];

    int Nv = in_sizes[0] / 5;
    int U  = in_sizes[2];
    int M  = out_size / 64;
    if (M <= 0) return;

    int nwin = U * 8;
    k_init<<<(nwin + 255) / 256, 256>>>(nwin, bs_w1, bs_w2);
    k_scatter<<<(Nv + 255) / 256, 256>>>(coords, inv, Nv);

    int NB = (U + 1023) / 1024;
    k_count<<<NB, 256>>>(cnt, U);
    k_compact<<<NB, 256>>>(cnt, U);

    {
        cudaFuncSetAttribute(k_rows2, cudaFuncAttributeMaxDynamicSharedMemorySize, R_SMEM);
        k_rows2<<<(M + 63) / 64, 256, R_SMEM>>>(vf, up_w1, up_b1, up_w2, up_b2,
                                                ca_w1, ca_w2, sa_conv, M);
    }

    {
        int dynsmem = 2 * G1_STAGE;
        cudaFuncSetAttribute(k_gemm1_mma, cudaFuncAttributeMaxDynamicSharedMemorySize, dynsmem);
        dim3 g1((M + 127) / 128, 2);
        k_gemm1_mma<<<g1, 256, dynsmem>>>(M);
    }

    {
        cudaFuncSetAttribute(k_gemm2_mma, cudaFuncAttributeMaxDynamicSharedMemorySize, G2_SMEM);
        k_gemm2_mma<<<(M + 127) / 128, 256, G2_SMEM>>>((float*)d_out, bn1_g, bn1_b,
                                                       1.f / (float)M, M);
    }
    k_final<<<(M * 64 + 255) / 256, 256>>>((float*)d_out, bn2_g, bn2_b,
                                           1.f / (float)M, M * 64);
}

// round 15
// speedup vs baseline: 1.2397x; 1.0052x over previous
#include <cuda_runtime.h>
#include <cuda_bf16.h>
#include <cuda_fp16.h>
#include <math.h>
#include <stdint.h>

// ---------------- static scratch (allocation-free) ----------------
#define UMAX 200000
__device__ int   g_winner[UMAX * 8];
__device__ int   g_selrows[UMAX];
__device__ int   g_bsum[256];
__device__ __align__(16) __half g_flat_h[(size_t)UMAX * 512];
__device__ __align__(16) __half g_wt_h[256 * 512];
__device__ __align__(16) __half g_w2t_h[64 * 256];
__device__ __align__(16) __half g_z1h[(size_t)UMAX * 256];
__device__ __align__(16) float g_stats1[512];   // sum[256] | sumsq[256]
__device__ __align__(16) float g_stats2[128];   // sum[64]  | sumsq[64]

__device__ __forceinline__ uint32_t smem_u32(const void* p) {
    uint32_t a;
    asm("{ .reg .u64 t; cvta.to.shared.u64 t, %1; cvt.u32.u64 %0, t; }" : "=r"(a) : "l"(p));
    return a;
}

// ---------------- init + weight prep (merged) ----------------
__global__ void k_init(int nwin, const float* __restrict__ W1, const float* __restrict__ W2) {
    int i = blockIdx.x * blockDim.x + threadIdx.x;
    if (i < nwin) g_winner[i] = -1;
    if (i < 512)  g_stats1[i] = 0.f;
    if (i < 128)  g_stats2[i] = 0.f;
    if (i < 131072) {
        int n = i >> 9, k = i & 511;
        g_wt_h[i] = __float2half(W1[(size_t)k * 256 + n]);
    }
    if (i < 16384) {
        int n = i >> 8, k = i & 255;
        g_w2t_h[i] = __float2half(W2[(size_t)k * 64 + n]);
    }
}

// ---------------- scatter: last-write-wins via max voxel index ----------------
__global__ void k_scatter(const int* __restrict__ coords, const int* __restrict__ inv, int Nv) {
    int i = blockIdx.x * blockDim.x + threadIdx.x;
    if (i < Nv) {
        int z = coords[(size_t)i * 4 + 1];
        int u = inv[i];
        atomicMax(&g_winner[(size_t)u * 8 + z], i);
    }
}

// ---------------- compaction: count per 1024-block ----------------
__global__ void k_count(const int* __restrict__ cnt, int U) {
    __shared__ int s[256];
    int base = blockIdx.x * 1024;
    int c = 0;
    for (int t = threadIdx.x; t < 1024; t += 256) {
        int u = base + t;
        if (u < U && cnt[u] >= 2) c++;
    }
    s[threadIdx.x] = c;
    __syncthreads();
    for (int o = 128; o > 0; o >>= 1) {
        if (threadIdx.x < o) s[threadIdx.x] += s[threadIdx.x + o];
        __syncthreads();
    }
    if (threadIdx.x == 0) g_bsum[blockIdx.x] = s[0];
}

// ---------------- compaction: in-block scan + self-computed block prefix ----------------
__global__ void k_compact(const int* __restrict__ cnt, int U) {
    __shared__ int s[256];
    __shared__ int spre[256];
    __shared__ int s_off;
    int tid = threadIdx.x;
    {
        int acc = 0;
        for (int i = tid; i < blockIdx.x; i += 256) acc += g_bsum[i];
        spre[tid] = acc;
        __syncthreads();
        for (int o = 128; o > 0; o >>= 1) {
            if (tid < o) spre[tid] += spre[tid + o];
            __syncthreads();
        }
        if (tid == 0) s_off = spre[0];
        __syncthreads();
    }
    int base = blockIdx.x * 1024 + tid * 4;
    int flags[4]; int c = 0;
    for (int q = 0; q < 4; q++) {
        int u = base + q;
        flags[q] = (u < U && cnt[u] >= 2) ? 1 : 0;
        c += flags[q];
    }
    s[tid] = c;
    __syncthreads();
    for (int o = 1; o < 256; o <<= 1) {
        int v = (tid >= o) ? s[tid - o] : 0;
        __syncthreads();
        s[tid] += v;
        __syncthreads();
    }
    int off = s_off + s[tid] - c;
    for (int q = 0; q < 4; q++) {
        if (flags[q]) g_selrows[off++] = base + q;
    }
}

// ---------------- common mma macros ----------------
#define LDSM4(R0, R1, R2, R3, ADDR) \
    asm volatile("ldmatrix.sync.aligned.m8n8.x4.shared.b16 {%0,%1,%2,%3}, [%4];" \
                 : "=r"(R0), "=r"(R1), "=r"(R2), "=r"(R3) : "r"(ADDR))

#define MMA16816F16(D, A, B) \
    asm volatile("mma.sync.aligned.m16n8k16.row.col.f32.f16.f16.f32 " \
                 "{%0,%1,%2,%3}, {%4,%5,%6,%7}, {%8,%9}, {%0,%1,%2,%3};" \
                 : "+f"((D)[0]), "+f"((D)[1]), "+f"((D)[2]), "+f"((D)[3]) \
                 : "r"((A)[0]), "r"((A)[1]), "r"((A)[2]), "r"((A)[3]), \
                   "r"((B)[0]), "r"((B)[1]))

__device__ __forceinline__ void cp16z(uint32_t saddr, const void* gaddr, uint32_t sz) {
    asm volatile("cp.async.cg.shared.global [%0], [%1], 16, %2;"
                 :: "r"(saddr), "l"(gaddr), "r"(sz));
}

// ---------------- k_rows2: slot MLP (tensorized hi/lo) + CBAM + flatten ----------------
#define R_W2H   0
#define R_W2L   5120
#define R_WARP0 10240
#define R_WSTR  7488
#define R_HIDH  0
#define R_HIDL  1280
#define R_XBUF  2560
#define R_FEAT  7168
#define R_BC    70144
#define R_SMEM  75328

__global__ void __launch_bounds__(256, 2)
k_rows2(const float* __restrict__ vf,
        const float* __restrict__ w1, const float* __restrict__ b1,
        const float* __restrict__ w2g, const float* __restrict__ b2,
        const float* __restrict__ caw1, const float* __restrict__ caw2,
        const float* __restrict__ saconv, int M)
{
    extern __shared__ __align__(16) char dsm[];
    uint32_t sbase = smem_u32(dsm);
    float* bc = (float*)(dsm + R_BC);
    float* sw1f  = bc + 0;
    float* sb1f  = bc + 160;
    float* sb2f  = bc + 192;
    float* scw1f = bc + 256;
    float* scw2f = bc + 768;
    float* sconvf = bc + 1280;

    const unsigned FULL = 0xffffffffu;
    int tid  = threadIdx.x;
    int wid  = tid >> 5;
    int lane = tid & 31;
    int row0 = blockIdx.x * 64;

    for (int i = tid; i < 160; i += 256) sw1f[i] = w1[i];
    if (tid < 32) sb1f[tid] = b1[tid];
    if (tid < 64) sb2f[tid] = b2[tid];
    for (int i = tid; i < 512; i += 256) scw1f[i] = caw1[i];
    for (int i = tid; i < 512; i += 256) scw2f[i] = caw2[i];
    if (tid < 14) sconvf[tid] = saconv[tid];

    for (int i = tid; i < 2048; i += 256) {
        int n = i >> 5, k = i & 31;
        float w = w2g[k * 64 + n];
        __half hh = __float2half(w);
        float lo = w - __half2float(hh);
        *(__half*)(dsm + R_W2H + n * 80 + k * 2) = hh;
        *(__half*)(dsm + R_W2L + n * 80 + k * 2) = __float2half(lo);
    }
    __syncthreads();

    uint32_t wbase = sbase + R_WARP0 + (uint32_t)wid * R_WSTR;
    float* featp = (float*)(dsm + R_WARP0 + wid * R_WSTR + R_FEAT);
    float* xb    = (float*)(dsm + R_WARP0 + wid * R_WSTR + R_XBUF);
    __half* hidh = (__half*)(dsm + R_WARP0 + wid * R_WSTR + R_HIDH);
    __half* hidl = (__half*)(dsm + R_WARP0 + wid * R_WSTR + R_HIDL);

    uint32_t aColB = (uint32_t)((lane >> 4) * 16);
    uint32_t aRowO = (uint32_t)((lane & 15) * 80);
    uint32_t bRowB = (uint32_t)(((lane >> 4) & 1) * 8 + (lane & 7));
    uint32_t bColB = (uint32_t)(((lane >> 3) & 1) * 16);

    for (int rp = 0; rp < 4; rp++) {
        int j0 = row0 + wid * 8 + rp * 2;
        if (j0 >= M) break;

#pragma unroll
        for (int rr = 0; rr < 2; rr++) {
            int j = j0 + rr;
            int valid = (j < M);
            int u = valid ? g_selrows[j] : 0;
            int wv = (valid && lane < 8) ? g_winner[(size_t)u * 8 + lane] : -1;
#pragma unroll
            for (int q = 0; q < 2; q++) {
                int t = lane + q * 32;
                int tv = (t < 40);
                int zz = tv ? (t / 5) : 0;
                int f  = t - zz * 5;
                int w = __shfl_sync(FULL, wv, zz);
                if (tv) featp[rr * 40 + t] = (w >= 0) ? vf[(size_t)w * 5 + f] : 0.f;
            }
        }
        __syncwarp();

#pragma unroll
        for (int z = 0; z < 16; z++) {
            const float* ft = featp + (z >> 3) * 40 + (z & 7) * 5;
            float a = sb1f[lane];
#pragma unroll
            for (int f = 0; f < 5; f++) a += ft[f] * sw1f[f * 32 + lane];
            a = fmaxf(a, 0.f);
            __half hh = __float2half(a);
            float lo = a - __half2float(hh);
            hidh[z * 40 + lane] = hh;
            hidl[z * 40 + lane] = __float2half(lo);
        }
        __syncwarp();

        float acc[8][4] = {};
#pragma unroll
        for (int kk = 0; kk < 2; kk++) {
            uint32_t kb = (uint32_t)(kk * 32);
            uint32_t ah[4], al[4];
            LDSM4(ah[0], ah[1], ah[2], ah[3], wbase + R_HIDH + aRowO + kb + aColB);
            LDSM4(al[0], al[1], al[2], al[3], wbase + R_HIDL + aRowO + kb + aColB);
            uint32_t bh[8][2], bl[8][2];
#pragma unroll
            for (int nh = 0; nh < 4; nh++) {
                uint32_t rofs = (uint32_t)(nh * 16 + bRowB) * 80 + kb + bColB;
                uint32_t t0, t1, t2, t3;
                LDSM4(t0, t1, t2, t3, sbase + R_W2H + rofs);
                bh[nh * 2][0] = t0; bh[nh * 2][1] = t1;
                bh[nh * 2 + 1][0] = t2; bh[nh * 2 + 1][1] = t3;
                LDSM4(t0, t1, t2, t3, sbase + R_W2L + rofs);
                bl[nh * 2][0] = t0; bl[nh * 2][1] = t1;
                bl[nh * 2 + 1][0] = t2; bl[nh * 2 + 1][1] = t3;
            }
#pragma unroll
            for (int ni = 0; ni < 8; ni++) {
                MMA16816F16(acc[ni], ah, bh[ni]);
                MMA16816F16(acc[ni], ah, bl[ni]);
                MMA16816F16(acc[ni], al, bh[ni]);
            }
        }

        {
            int r0 = lane >> 2, c0 = (lane & 3) * 2;
#pragma unroll
            for (int ni = 0; ni < 8; ni++) {
                *(float2*)&xb[r0 * 72 + ni * 8 + c0]       = make_float2(acc[ni][0], acc[ni][1]);
                *(float2*)&xb[(r0 + 8) * 72 + ni * 8 + c0] = make_float2(acc[ni][2], acc[ni][3]);
            }
        }
        __syncwarp();

#pragma unroll
        for (int rr = 0; rr < 2; rr++) {
            int j = j0 + rr;
            float x0[8], x1[8];
#pragma unroll
            for (int z = 0; z < 8; z++) {
                x0[z] = xb[(rr * 8 + z) * 72 + lane]      + sb2f[lane];
                x1[z] = xb[(rr * 8 + z) * 72 + lane + 32] + sb2f[lane + 32];
            }

            float m0 = 0.f, m1 = 0.f, q0 = -3.4e38f, q1 = -3.4e38f;
#pragma unroll
            for (int z = 0; z < 8; z++) {
                m0 += x0[z]; m1 += x1[z];
                q0 = fmaxf(q0, x0[z]); q1 = fmaxf(q1, x1[z]);
            }
            m0 *= 0.125f; m1 *= 0.125f;

            float s8[8];
#pragma unroll
            for (int r8 = 0; r8 < 8; r8++) {
                float pm = m0 * scw1f[lane * 8 + r8] + m1 * scw1f[(lane + 32) * 8 + r8];
                float px = q0 * scw1f[lane * 8 + r8] + q1 * scw1f[(lane + 32) * 8 + r8];
#pragma unroll
                for (int o = 16; o > 0; o >>= 1) {
                    pm += __shfl_xor_sync(FULL, pm, o);
                    px += __shfl_xor_sync(FULL, px, o);
                }
                s8[r8] = fmaxf(pm, 0.f) + fmaxf(px, 0.f);
            }

            float a0 = 0.f, a1 = 0.f;
#pragma unroll
            for (int r8 = 0; r8 < 8; r8++) {
                a0 += s8[r8] * scw2f[r8 * 64 + lane];
                a1 += s8[r8] * scw2f[r8 * 64 + lane + 32];
            }
            float ca0 = 1.f / (1.f + expf(-a0));
            float ca1 = 1.f / (1.f + expf(-a1));
#pragma unroll
            for (int z = 0; z < 8; z++) { x0[z] *= ca0; x1[z] *= ca1; }

            float szm[8], szx[8];
#pragma unroll
            for (int z = 0; z < 8; z++) {
                float s = x0[z] + x1[z];
                float m = fmaxf(x0[z], x1[z]);
#pragma unroll
                for (int o = 16; o > 0; o >>= 1) {
                    s += __shfl_xor_sync(FULL, s, o);
                    m = fmaxf(m, __shfl_xor_sync(FULL, m, o));
                }
                szm[z] = s * (1.f / 64.f);
                szx[z] = m;
            }

            float sav = 0.f;
            if (lane < 8) {
                float acc2 = 0.f;
#pragma unroll
                for (int t = 0; t < 7; t++) {
                    int p = lane + t - 3;
                    if (p >= 0 && p < 8) acc2 += szm[p] * sconvf[t] + szx[p] * sconvf[7 + t];
                }
                sav = 1.f / (1.f + expf(-acc2));
            }
            float sa[8];
#pragma unroll
            for (int z = 0; z < 8; z++) sa[z] = __shfl_sync(FULL, sav, z);

            if (j < M) {
                size_t base = (size_t)j * 512;
                uint32_t ph[4];
#pragma unroll
                for (int z2 = 0; z2 < 4; z2++) {
                    __half2 h2 = __floats2half2_rn(x0[2 * z2] * sa[2 * z2], x0[2 * z2 + 1] * sa[2 * z2 + 1]);
                    ph[z2] = *(uint32_t*)&h2;
                }
                *(uint4*)&g_flat_h[base + lane * 8] = *(uint4*)ph;
#pragma unroll
                for (int z2 = 0; z2 < 4; z2++) {
                    __half2 h2 = __floats2half2_rn(x1[2 * z2] * sa[2 * z2], x1[2 * z2 + 1] * sa[2 * z2 + 1]);
                    ph[z2] = *(uint32_t*)&h2;
                }
                *(uint4*)&g_flat_h[base + (lane + 32) * 8] = *(uint4*)ph;
            }
        }
        __syncwarp();
    }
}

// ---------------- GEMM1 (mma.sync fp16 single-pass, 128x128 tile) + fused bn1 stats ----------------
// grid = (2 col-blocks, M/128 row-blocks): col-pairs launch-adjacent -> A tile L2 reuse
#define G1_PITCHB  144
#define G1_A_OFF   0
#define G1_B_OFF   18432
#define G1_STAGE   36864

__global__ void __launch_bounds__(256, 2)
k_gemm1_mma(int M) {
    extern __shared__ __align__(16) char dsm[];
    uint32_t sbase = smem_u32(dsm);
    const unsigned FULL = 0xffffffffu;

    int tid  = threadIdx.x;
    int lane = tid & 31;
    int wid  = tid >> 5;
    int wm = wid & 1;
    int wn = wid >> 1;
    int row0 = blockIdx.y * 128;
    int col0 = blockIdx.x * 128;

    int li_r  = tid >> 3;
    int li_c8 = tid & 7;

    float acc[4][4][4] = {};

    auto load_chunk = [&](int c) {
        uint32_t st = sbase + (uint32_t)(c & 1) * G1_STAGE;
#pragma unroll
        for (int it = 0; it < 4; it++) {
            int r = li_r + it * 32;
            int gr = row0 + r;
            uint32_t soff = (uint32_t)(r * G1_PITCHB + li_c8 * 16);
            size_t goff = (size_t)gr * 512 + c * 64 + li_c8 * 8;
            uint32_t sz = (gr < M) ? 16u : 0u;
            cp16z(st + G1_A_OFF + soff, g_flat_h + goff, sz);
            int n = col0 + r;
            size_t boff = (size_t)n * 512 + c * 64 + li_c8 * 8;
            cp16z(st + G1_B_OFF + soff, g_wt_h + boff, 16u);
        }
        asm volatile("cp.async.commit_group;");
    };

    load_chunk(0);

    uint32_t aRow  = (uint32_t)(wm * 64 + (lane & 15));
    uint32_t aColB = (uint32_t)((lane >> 4) * 16);
    uint32_t bRow  = (uint32_t)(wn * 32 + ((lane >> 4) & 1) * 8 + (lane & 7));
    uint32_t bColB = (uint32_t)(((lane >> 3) & 1) * 16);

    for (int c = 0; c < 8; c++) {
        if (c < 7) load_chunk(c + 1);
        if (c < 7) { asm volatile("cp.async.wait_group 1;"); }
        else       { asm volatile("cp.async.wait_group 0;"); }
        __syncthreads();

        uint32_t st = sbase + (uint32_t)(c & 1) * G1_STAGE;
#pragma unroll
        for (int kk = 0; kk < 4; kk++) {
            uint32_t kb = (uint32_t)(kk * 32);
            uint32_t ah[4][4];
#pragma unroll
            for (int mi = 0; mi < 4; mi++) {
                uint32_t ad = st + G1_A_OFF + (aRow + mi * 16) * G1_PITCHB + kb + aColB;
                LDSM4(ah[mi][0], ah[mi][1], ah[mi][2], ah[mi][3], ad);
            }
            uint32_t bh[4][2];
#pragma unroll
            for (int nh = 0; nh < 2; nh++) {
                uint32_t bd = st + G1_B_OFF + (bRow + nh * 16) * G1_PITCHB + kb + bColB;
                uint32_t t0, t1, t2, t3;
                LDSM4(t0, t1, t2, t3, bd);
                bh[nh * 2][0] = t0; bh[nh * 2][1] = t1;
                bh[nh * 2 + 1][0] = t2; bh[nh * 2 + 1][1] = t3;
            }
#pragma unroll
            for (int mi = 0; mi < 4; mi++) {
#pragma unroll
                for (int ni = 0; ni < 4; ni++) {
                    MMA16816F16(acc[mi][ni], ah[mi], bh[ni]);
                }
            }
        }
        __syncthreads();
    }

#pragma unroll
    for (int mi = 0; mi < 4; mi++) {
#pragma unroll
        for (int ni = 0; ni < 4; ni++) {
            int grow = row0 + wm * 64 + mi * 16 + (lane >> 2);
            int gcol = col0 + wn * 32 + ni * 8 + (lane & 3) * 2;
            if (grow < M) {
                __half2 h = __floats2half2_rn(acc[mi][ni][0], acc[mi][ni][1]);
                *(uint32_t*)(g_z1h + (size_t)grow * 256 + gcol) = *(uint32_t*)&h;
            }
            if (grow + 8 < M) {
                __half2 h = __floats2half2_rn(acc[mi][ni][2], acc[mi][ni][3]);
                *(uint32_t*)(g_z1h + (size_t)(grow + 8) * 256 + gcol) = *(uint32_t*)&h;
            }
        }
    }

#pragma unroll
    for (int ni = 0; ni < 4; ni++) {
#pragma unroll
        for (int jj = 0; jj < 2; jj++) {
            float s = 0.f, s2 = 0.f;
#pragma unroll
            for (int mi = 0; mi < 4; mi++) {
                float v0 = acc[mi][ni][jj], v1 = acc[mi][ni][jj + 2];
                s += v0 + v1; s2 += v0 * v0 + v1 * v1;
            }
#pragma unroll
            for (int o = 4; o <= 16; o <<= 1) {
                s  += __shfl_xor_sync(FULL, s, o);
                s2 += __shfl_xor_sync(FULL, s2, o);
            }
            if ((lane >> 2) == 0) {
                int col = col0 + wn * 32 + ni * 8 + (lane & 3) * 2 + jj;
                atomicAdd(&g_stats1[col], s);
                atomicAdd(&g_stats1[256 + col], s2);
            }
        }
    }
}

// ---------------- GEMM2 (mma.sync fp16 single-pass): bn1 params computed in-kernel ----------------
#define G2_PITCHB  144
#define G2_A_OFF   0
#define G2_B_OFF   18432
#define G2_SMEM    27648

__global__ void __launch_bounds__(256, 2)
k_gemm2_mma(float* __restrict__ out,
            const float* __restrict__ bn1g, const float* __restrict__ bn1b,
            float invM, int M) {
    extern __shared__ __align__(16) char dsm2[];
    uint32_t sbase = smem_u32(dsm2);
    __shared__ float ss[128];
    __shared__ float sbn_sc[256], sbn_sh[256];
    const unsigned FULL = 0xffffffffu;

    int tid  = threadIdx.x;
    int lane = tid & 31;
    int wid  = tid >> 5;
    int row0 = blockIdx.x * 128;

    if (tid < 128) ss[tid] = 0.f;
    {
        float mu  = g_stats1[tid] * invM;
        float var = g_stats1[256 + tid] * invM - mu * mu;
        float s = bn1g[tid] * rsqrtf(var + 0.001f);
        sbn_sc[tid] = s;
        sbn_sh[tid] = bn1b[tid] - mu * s;
    }

    float acc[8][4] = {};

    uint32_t aRow  = (uint32_t)(wid * 16 + (lane & 15));
    uint32_t aColB = (uint32_t)((lane >> 4) * 16);
    uint32_t bRowB = (uint32_t)(((lane >> 4) & 1) * 8 + (lane & 7));
    uint32_t bColB = (uint32_t)(((lane >> 3) & 1) * 16);

    for (int c = 0; c < 4; c++) {
        __syncthreads();
        {
            int f4 = tid & 3;
            int colb = f4 * 16;
#pragma unroll
            for (int half = 0; half < 2; half++) {
                int r = (tid >> 2) + half * 64;
                int gr = row0 + r;
                uint32_t hv[8] = {};
                if (gr < M) {
                    const uint4* src = (const uint4*)(g_z1h + (size_t)gr * 256 + c * 64 + colb);
                    *(uint4*)&hv[0] = src[0];
                    *(uint4*)&hv[4] = src[1];
                }
                uint32_t outp[8];
#pragma unroll
                for (int p = 0; p < 8; p++) {
                    __half2 h2 = *(__half2*)&hv[p];
                    float2 v = __half22float2(h2);
                    int col = c * 64 + colb + p * 2;
                    float y0 = (gr < M) ? fmaxf(v.x * sbn_sc[col] + sbn_sh[col], 0.f) : 0.f;
                    float y1 = (gr < M) ? fmaxf(v.y * sbn_sc[col + 1] + sbn_sh[col + 1], 0.f) : 0.f;
                    __half2 o = __floats2half2_rn(y0, y1);
                    outp[p] = *(uint32_t*)&o;
                }
                uint32_t off = (uint32_t)(r * G2_PITCHB + colb * 2);
                *(uint4*)(dsm2 + G2_A_OFF + off)      = *(uint4*)&outp[0];
                *(uint4*)(dsm2 + G2_A_OFF + off + 16) = *(uint4*)&outp[4];
            }
        }
        {
            int n = tid >> 2;
            int kg = (tid & 3) * 16;
            const uint4* gh = (const uint4*)(g_w2t_h + (size_t)n * 256 + c * 64 + kg);
            uint32_t off = (uint32_t)(n * G2_PITCHB + kg * 2);
            *(uint4*)(dsm2 + G2_B_OFF + off)      = gh[0];
            *(uint4*)(dsm2 + G2_B_OFF + off + 16) = gh[1];
        }
        __syncthreads();

#pragma unroll
        for (int kk = 0; kk < 4; kk++) {
            uint32_t kb = (uint32_t)(kk * 32);
            uint32_t ah[4];
            {
                uint32_t ad = sbase + G2_A_OFF + aRow * G2_PITCHB + kb + aColB;
                LDSM4(ah[0], ah[1], ah[2], ah[3], ad);
            }
            uint32_t bh[8][2];
#pragma unroll
            for (int nh = 0; nh < 4; nh++) {
                uint32_t bd = sbase + G2_B_OFF + (nh * 16 + bRowB) * G2_PITCHB + kb + bColB;
                uint32_t t0, t1, t2, t3;
                LDSM4(t0, t1, t2, t3, bd);
                bh[nh * 2][0] = t0; bh[nh * 2][1] = t1;
                bh[nh * 2 + 1][0] = t2; bh[nh * 2 + 1][1] = t3;
            }
#pragma unroll
            for (int ni = 0; ni < 8; ni++) {
                MMA16816F16(acc[ni], ah, bh[ni]);
            }
        }
    }

    int grow = row0 + wid * 16 + (lane >> 2);
#pragma unroll
    for (int ni = 0; ni < 8; ni++) {
        int gcol = ni * 8 + (lane & 3) * 2;
        if (grow < M)
            *(float2*)(out + (size_t)grow * 64 + gcol) = make_float2(acc[ni][0], acc[ni][1]);
        if (grow + 8 < M)
            *(float2*)(out + (size_t)(grow + 8) * 64 + gcol) = make_float2(acc[ni][2], acc[ni][3]);
    }

#pragma unroll
    for (int ni = 0; ni < 8; ni++) {
#pragma unroll
        for (int jj = 0; jj < 2; jj++) {
            float s = acc[ni][jj] + acc[ni][jj + 2];
            float s2 = acc[ni][jj] * acc[ni][jj] + acc[ni][jj + 2] * acc[ni][jj + 2];
#pragma unroll
            for (int o = 4; o <= 16; o <<= 1) {
                s  += __shfl_xor_sync(FULL, s, o);
                s2 += __shfl_xor_sync(FULL, s2, o);
            }
            if ((lane >> 2) == 0) {
                int col = ni * 8 + (lane & 3) * 2 + jj;
                atomicAdd(&ss[col], s);
                atomicAdd(&ss[64 + col], s2);
            }
        }
    }
    __syncthreads();
    if (tid < 128) atomicAdd(&g_stats2[tid], ss[tid]);
}

// ---------------- final: bn2 params computed in-kernel + normalize ----------------
__global__ void k_final(float* __restrict__ out,
                        const float* __restrict__ bn2g, const float* __restrict__ bn2b,
                        float invM, int n) {
    __shared__ float sc[64], sh[64];
    if (threadIdx.x < 64) {
        int c = threadIdx.x;
        float mu  = g_stats2[c] * invM;
        float var = g_stats2[64 + c] * invM - mu * mu;
        float s = bn2g[c] * rsqrtf(var + 0.001f);
        sc[c] = s;
        sh[c] = bn2b[c] - mu * s;
    }
    __syncthreads();
    int i = blockIdx.x * blockDim.x + threadIdx.x;
    if (i < n) {
        int c = i & 63;
        out[i] = fmaxf(out[i] * sc[c] + sh[c], 0.f);
    }
}

// ---------------- launcher ----------------
extern "C" void kernel_launch(void* const* d_in, const int* in_sizes, int n_in,
                              void* d_out, int out_size) {
    const float* vf      = (const float*)d_in[0];
    const int*   coords  = (const int*)d_in[1];
    const int*   inv     = (const int*)d_in[3];
    const int*   cnt     = (const int*)d_in[4];
    const float* up_w1   = (const float*)d_in[5];
    const float* up_b1   = (const float*)d_in[6];
    const float* up_w2   = (const float*)d_in[7];
    const float* up_b2   = (const float*)d_in[8];
    const float* ca_w1   = (const float*)d_in[9];
    const float* ca_w2   = (const float*)d_in[10];
    const float* sa_conv = (const float*)d_in[11];
    const float* bs_w1   = (const float*)d_in[12];
    const float* bn1_g   = (const float*)d_in[13];
    const float* bn1_b   = (const float*)d_in[14];
    const float* bs_w2   = (const float*)d_in[15];
    const float* bn2_g   = (const float*)d_in[16];
    const float* bn2_b   = (const float*)d_in[17];

    int Nv = in_sizes[0] / 5;
    int U  = in_sizes[2];
    int M  = out_size / 64;
    if (M <= 0) return;

    int nwin = U * 8;
    k_init<<<(nwin + 255) / 256, 256>>>(nwin, bs_w1, bs_w2);
    k_scatter<<<(Nv + 255) / 256, 256>>>(coords, inv, Nv);

    int NB = (U + 1023) / 1024;
    k_count<<<NB, 256>>>(cnt, U);
    k_compact<<<NB, 256>>>(cnt, U);

    {
        cudaFuncSetAttribute(k_rows2, cudaFuncAttributeMaxDynamicSharedMemorySize, R_SMEM);
        k_rows2<<<(M + 63) / 64, 256, R_SMEM>>>(vf, up_w1, up_b1, up_w2, up_b2,
                                                ca_w1, ca_w2, sa_conv, M);
    }

    {
        int dynsmem = 2 * G1_STAGE;
        cudaFuncSetAttribute(k_gemm1_mma, cudaFuncAttributeMaxDynamicSharedMemorySize, dynsmem);
        dim3 g1(2, (M + 127) / 128);
        k_gemm1_mma<<<g1, 256, dynsmem>>>(M);
    }

    {
        cudaFuncSetAttribute(k_gemm2_mma, cudaFuncAttributeMaxDynamicSharedMemorySize, G2_SMEM);
        k_gemm2_mma<<<(M + 127) / 128, 256, G2_SMEM>>>((float*)d_out, bn1_g, bn1_b,
                                                       1.f / (float)M, M);
    }
    k_final<<<(M * 64 + 255) / 256, 256>>>((float*)d_out, bn2_g, bn2_b,
                                           1.f / (float)M, M * 64);
}

// round 16
// speedup vs baseline: 1.2459x; 1.0050x over previous
#include <cuda_runtime.h>
#include <cuda_bf16.h>
#include <cuda_fp16.h>
#include <math.h>
#include <stdint.h>

// ---------------- static scratch (allocation-free) ----------------
#define UMAX 200000
__device__ int   g_winner[UMAX * 8];
__device__ int   g_selrows[UMAX];
__device__ int   g_bsum[256];
__device__ __align__(16) __half g_flat_h[(size_t)UMAX * 512];
__device__ __align__(16) __half g_wt_h[256 * 512];
__device__ __align__(16) __half g_w2t_h[64 * 256];
__device__ __align__(16) __half g_z1h[(size_t)UMAX * 256];
__device__ __align__(16) float g_stats1[512];   // sum[256] | sumsq[256]
__device__ __align__(16) float g_stats2[128];   // sum[64]  | sumsq[64]

__device__ __forceinline__ uint32_t smem_u32(const void* p) {
    uint32_t a;
    asm("{ .reg .u64 t; cvta.to.shared.u64 t, %1; cvt.u32.u64 %0, t; }" : "=r"(a) : "l"(p));
    return a;
}

// ---------------- init + weight prep (merged) ----------------
__global__ void k_init(int nwin, const float* __restrict__ W1, const float* __restrict__ W2) {
    int i = blockIdx.x * blockDim.x + threadIdx.x;
    if (i < nwin) g_winner[i] = -1;
    if (i < 512)  g_stats1[i] = 0.f;
    if (i < 128)  g_stats2[i] = 0.f;
    if (i < 131072) {
        int n = i >> 9, k = i & 511;
        g_wt_h[i] = __float2half(W1[(size_t)k * 256 + n]);
    }
    if (i < 16384) {
        int n = i >> 8, k = i & 255;
        g_w2t_h[i] = __float2half(W2[(size_t)k * 64 + n]);
    }
}

// ---------------- scatter: last-write-wins via max voxel index ----------------
__global__ void k_scatter(const int* __restrict__ coords, const int* __restrict__ inv, int Nv) {
    int i = blockIdx.x * blockDim.x + threadIdx.x;
    if (i < Nv) {
        int z = coords[(size_t)i * 4 + 1];
        int u = inv[i];
        atomicMax(&g_winner[(size_t)u * 8 + z], i);
    }
}

// ---------------- compaction: count per 1024-block ----------------
__global__ void k_count(const int* __restrict__ cnt, int U) {
    __shared__ int s[256];
    int base = blockIdx.x * 1024;
    int c = 0;
    for (int t = threadIdx.x; t < 1024; t += 256) {
        int u = base + t;
        if (u < U && cnt[u] >= 2) c++;
    }
    s[threadIdx.x] = c;
    __syncthreads();
    for (int o = 128; o > 0; o >>= 1) {
        if (threadIdx.x < o) s[threadIdx.x] += s[threadIdx.x + o];
        __syncthreads();
    }
    if (threadIdx.x == 0) g_bsum[blockIdx.x] = s[0];
}

// ---------------- compaction: in-block scan + self-computed block prefix ----------------
__global__ void k_compact(const int* __restrict__ cnt, int U) {
    __shared__ int s[256];
    __shared__ int spre[256];
    __shared__ int s_off;
    int tid = threadIdx.x;
    {
        int acc = 0;
        for (int i = tid; i < blockIdx.x; i += 256) acc += g_bsum[i];
        spre[tid] = acc;
        __syncthreads();
        for (int o = 128; o > 0; o >>= 1) {
            if (tid < o) spre[tid] += spre[tid + o];
            __syncthreads();
        }
        if (tid == 0) s_off = spre[0];
        __syncthreads();
    }
    int base = blockIdx.x * 1024 + tid * 4;
    int flags[4]; int c = 0;
    for (int q = 0; q < 4; q++) {
        int u = base + q;
        flags[q] = (u < U && cnt[u] >= 2) ? 1 : 0;
        c += flags[q];
    }
    s[tid] = c;
    __syncthreads();
    for (int o = 1; o < 256; o <<= 1) {
        int v = (tid >= o) ? s[tid - o] : 0;
        __syncthreads();
        s[tid] += v;
        __syncthreads();
    }
    int off = s_off + s[tid] - c;
    for (int q = 0; q < 4; q++) {
        if (flags[q]) g_selrows[off++] = base + q;
    }
}

// ---------------- common mma macros ----------------
#define LDSM4(R0, R1, R2, R3, ADDR) \
    asm volatile("ldmatrix.sync.aligned.m8n8.x4.shared.b16 {%0,%1,%2,%3}, [%4];" \
                 : "=r"(R0), "=r"(R1), "=r"(R2), "=r"(R3) : "r"(ADDR))

#define MMA16816F16(D, A, B) \
    asm volatile("mma.sync.aligned.m16n8k16.row.col.f32.f16.f16.f32 " \
                 "{%0,%1,%2,%3}, {%4,%5,%6,%7}, {%8,%9}, {%0,%1,%2,%3};" \
                 : "+f"((D)[0]), "+f"((D)[1]), "+f"((D)[2]), "+f"((D)[3]) \
                 : "r"((A)[0]), "r"((A)[1]), "r"((A)[2]), "r"((A)[3]), \
                   "r"((B)[0]), "r"((B)[1]))

__device__ __forceinline__ void cp16z(uint32_t saddr, const void* gaddr, uint32_t sz) {
    asm volatile("cp.async.cg.shared.global [%0], [%1], 16, %2;"
                 :: "r"(saddr), "l"(gaddr), "r"(sz));
}

// ---------------- k_rows2: slot MLP (tensorized hi/lo) + CBAM + flatten ----------------
#define R_W2H   0
#define R_W2L   5120
#define R_WARP0 10240
#define R_WSTR  7488
#define R_HIDH  0
#define R_HIDL  1280
#define R_XBUF  2560
#define R_FEAT  7168
#define R_BC    70144
#define R_SMEM  75328

__global__ void __launch_bounds__(256, 2)
k_rows2(const float* __restrict__ vf,
        const float* __restrict__ w1, const float* __restrict__ b1,
        const float* __restrict__ w2g, const float* __restrict__ b2,
        const float* __restrict__ caw1, const float* __restrict__ caw2,
        const float* __restrict__ saconv, int M)
{
    extern __shared__ __align__(16) char dsm[];
    uint32_t sbase = smem_u32(dsm);
    float* bc = (float*)(dsm + R_BC);
    float* sw1f  = bc + 0;
    float* sb1f  = bc + 160;
    float* sb2f  = bc + 192;
    float* scw1f = bc + 256;
    float* scw2f = bc + 768;
    float* sconvf = bc + 1280;

    const unsigned FULL = 0xffffffffu;
    int tid  = threadIdx.x;
    int wid  = tid >> 5;
    int lane = tid & 31;
    int row0 = blockIdx.x * 64;

    for (int i = tid; i < 160; i += 256) sw1f[i] = w1[i];
    if (tid < 32) sb1f[tid] = b1[tid];
    if (tid < 64) sb2f[tid] = b2[tid];
    for (int i = tid; i < 512; i += 256) scw1f[i] = caw1[i];
    for (int i = tid; i < 512; i += 256) scw2f[i] = caw2[i];
    if (tid < 14) sconvf[tid] = saconv[tid];

    for (int i = tid; i < 2048; i += 256) {
        int n = i >> 5, k = i & 31;
        float w = w2g[k * 64 + n];
        __half hh = __float2half(w);
        float lo = w - __half2float(hh);
        *(__half*)(dsm + R_W2H + n * 80 + k * 2) = hh;
        *(__half*)(dsm + R_W2L + n * 80 + k * 2) = __float2half(lo);
    }
    __syncthreads();

    uint32_t wbase = sbase + R_WARP0 + (uint32_t)wid * R_WSTR;
    float* featp = (float*)(dsm + R_WARP0 + wid * R_WSTR + R_FEAT);
    float* xb    = (float*)(dsm + R_WARP0 + wid * R_WSTR + R_XBUF);
    __half* hidh = (__half*)(dsm + R_WARP0 + wid * R_WSTR + R_HIDH);
    __half* hidl = (__half*)(dsm + R_WARP0 + wid * R_WSTR + R_HIDL);

    uint32_t aColB = (uint32_t)((lane >> 4) * 16);
    uint32_t aRowO = (uint32_t)((lane & 15) * 80);
    uint32_t bRowB = (uint32_t)(((lane >> 4) & 1) * 8 + (lane & 7));
    uint32_t bColB = (uint32_t)(((lane >> 3) & 1) * 16);

    for (int rp = 0; rp < 4; rp++) {
        int j0 = row0 + wid * 8 + rp * 2;
        if (j0 >= M) break;

#pragma unroll
        for (int rr = 0; rr < 2; rr++) {
            int j = j0 + rr;
            int valid = (j < M);
            int u = valid ? g_selrows[j] : 0;
            int wv = (valid && lane < 8) ? g_winner[(size_t)u * 8 + lane] : -1;
#pragma unroll
            for (int q = 0; q < 2; q++) {
                int t = lane + q * 32;
                int tv = (t < 40);
                int zz = tv ? (t / 5) : 0;
                int f  = t - zz * 5;
                int w = __shfl_sync(FULL, wv, zz);
                if (tv) featp[rr * 40 + t] = (w >= 0) ? vf[(size_t)w * 5 + f] : 0.f;
            }
        }
        __syncwarp();

#pragma unroll
        for (int z = 0; z < 16; z++) {
            const float* ft = featp + (z >> 3) * 40 + (z & 7) * 5;
            float a = sb1f[lane];
#pragma unroll
            for (int f = 0; f < 5; f++) a += ft[f] * sw1f[f * 32 + lane];
            a = fmaxf(a, 0.f);
            __half hh = __float2half(a);
            float lo = a - __half2float(hh);
            hidh[z * 40 + lane] = hh;
            hidl[z * 40 + lane] = __float2half(lo);
        }
        __syncwarp();

        float acc[8][4] = {};
#pragma unroll
        for (int kk = 0; kk < 2; kk++) {
            uint32_t kb = (uint32_t)(kk * 32);
            uint32_t ah[4], al[4];
            LDSM4(ah[0], ah[1], ah[2], ah[3], wbase + R_HIDH + aRowO + kb + aColB);
            LDSM4(al[0], al[1], al[2], al[3], wbase + R_HIDL + aRowO + kb + aColB);
            uint32_t bh[8][2], bl[8][2];
#pragma unroll
            for (int nh = 0; nh < 4; nh++) {
                uint32_t rofs = (uint32_t)(nh * 16 + bRowB) * 80 + kb + bColB;
                uint32_t t0, t1, t2, t3;
                LDSM4(t0, t1, t2, t3, sbase + R_W2H + rofs);
                bh[nh * 2][0] = t0; bh[nh * 2][1] = t1;
                bh[nh * 2 + 1][0] = t2; bh[nh * 2 + 1][1] = t3;
                LDSM4(t0, t1, t2, t3, sbase + R_W2L + rofs);
                bl[nh * 2][0] = t0; bl[nh * 2][1] = t1;
                bl[nh * 2 + 1][0] = t2; bl[nh * 2 + 1][1] = t3;
            }
#pragma unroll
            for (int ni = 0; ni < 8; ni++) {
                MMA16816F16(acc[ni], ah, bh[ni]);
                MMA16816F16(acc[ni], ah, bl[ni]);
                MMA16816F16(acc[ni], al, bh[ni]);
            }
        }

        {
            int r0 = lane >> 2, c0 = (lane & 3) * 2;
#pragma unroll
            for (int ni = 0; ni < 8; ni++) {
                *(float2*)&xb[r0 * 72 + ni * 8 + c0]       = make_float2(acc[ni][0], acc[ni][1]);
                *(float2*)&xb[(r0 + 8) * 72 + ni * 8 + c0] = make_float2(acc[ni][2], acc[ni][3]);
            }
        }
        __syncwarp();

#pragma unroll
        for (int rr = 0; rr < 2; rr++) {
            int j = j0 + rr;
            float x0[8], x1[8];
#pragma unroll
            for (int z = 0; z < 8; z++) {
                x0[z] = xb[(rr * 8 + z) * 72 + lane]      + sb2f[lane];
                x1[z] = xb[(rr * 8 + z) * 72 + lane + 32] + sb2f[lane + 32];
            }

            float m0 = 0.f, m1 = 0.f, q0 = -3.4e38f, q1 = -3.4e38f;
#pragma unroll
            for (int z = 0; z < 8; z++) {
                m0 += x0[z]; m1 += x1[z];
                q0 = fmaxf(q0, x0[z]); q1 = fmaxf(q1, x1[z]);
            }
            m0 *= 0.125f; m1 *= 0.125f;

            float s8[8];
#pragma unroll
            for (int r8 = 0; r8 < 8; r8++) {
                float pm = m0 * scw1f[lane * 8 + r8] + m1 * scw1f[(lane + 32) * 8 + r8];
                float px = q0 * scw1f[lane * 8 + r8] + q1 * scw1f[(lane + 32) * 8 + r8];
#pragma unroll
                for (int o = 16; o > 0; o >>= 1) {
                    pm += __shfl_xor_sync(FULL, pm, o);
                    px += __shfl_xor_sync(FULL, px, o);
                }
                s8[r8] = fmaxf(pm, 0.f) + fmaxf(px, 0.f);
            }

            float a0 = 0.f, a1 = 0.f;
#pragma unroll
            for (int r8 = 0; r8 < 8; r8++) {
                a0 += s8[r8] * scw2f[r8 * 64 + lane];
                a1 += s8[r8] * scw2f[r8 * 64 + lane + 32];
            }
            float ca0 = 1.f / (1.f + expf(-a0));
            float ca1 = 1.f / (1.f + expf(-a1));
#pragma unroll
            for (int z = 0; z < 8; z++) { x0[z] *= ca0; x1[z] *= ca1; }

            float szm[8], szx[8];
#pragma unroll
            for (int z = 0; z < 8; z++) {
                float s = x0[z] + x1[z];
                float m = fmaxf(x0[z], x1[z]);
#pragma unroll
                for (int o = 16; o > 0; o >>= 1) {
                    s += __shfl_xor_sync(FULL, s, o);
                    m = fmaxf(m, __shfl_xor_sync(FULL, m, o));
                }
                szm[z] = s * (1.f / 64.f);
                szx[z] = m;
            }

            float sav = 0.f;
            if (lane < 8) {
                float acc2 = 0.f;
#pragma unroll
                for (int t = 0; t < 7; t++) {
                    int p = lane + t - 3;
                    if (p >= 0 && p < 8) acc2 += szm[p] * sconvf[t] + szx[p] * sconvf[7 + t];
                }
                sav = 1.f / (1.f + expf(-acc2));
            }
            float sa[8];
#pragma unroll
            for (int z = 0; z < 8; z++) sa[z] = __shfl_sync(FULL, sav, z);

            if (j < M) {
                size_t base = (size_t)j * 512;
                uint32_t ph[4];
#pragma unroll
                for (int z2 = 0; z2 < 4; z2++) {
                    __half2 h2 = __floats2half2_rn(x0[2 * z2] * sa[2 * z2], x0[2 * z2 + 1] * sa[2 * z2 + 1]);
                    ph[z2] = *(uint32_t*)&h2;
                }
                *(uint4*)&g_flat_h[base + lane * 8] = *(uint4*)ph;
#pragma unroll
                for (int z2 = 0; z2 < 4; z2++) {
                    __half2 h2 = __floats2half2_rn(x1[2 * z2] * sa[2 * z2], x1[2 * z2 + 1] * sa[2 * z2 + 1]);
                    ph[z2] = *(uint32_t*)&h2;
                }
                *(uint4*)&g_flat_h[base + (lane + 32) * 8] = *(uint4*)ph;
            }
        }
        __syncwarp();
    }
}

// ---------------- GEMM1 (mma.sync fp16, 3-stage pipeline, 1 sync/chunk) + fused bn1 stats ----------------
#define G1_PITCHB  144
#define G1_A_OFF   0
#define G1_B_OFF   18432
#define G1_STAGE   36864

__global__ void __launch_bounds__(256, 2)
k_gemm1_mma(int M) {
    extern __shared__ __align__(16) char dsm[];
    uint32_t sbase = smem_u32(dsm);
    const unsigned FULL = 0xffffffffu;

    int tid  = threadIdx.x;
    int lane = tid & 31;
    int wid  = tid >> 5;
    int wm = wid & 1;
    int wn = wid >> 1;
    int row0 = blockIdx.y * 128;
    int col0 = blockIdx.x * 128;

    int li_r  = tid >> 3;
    int li_c8 = tid & 7;

    float acc[4][4][4] = {};

    auto load_chunk = [&](int c) {
        uint32_t st = sbase + (uint32_t)(c % 3) * G1_STAGE;
#pragma unroll
        for (int it = 0; it < 4; it++) {
            int r = li_r + it * 32;
            int gr = row0 + r;
            uint32_t soff = (uint32_t)(r * G1_PITCHB + li_c8 * 16);
            size_t goff = (size_t)gr * 512 + c * 64 + li_c8 * 8;
            uint32_t sz = (gr < M) ? 16u : 0u;
            cp16z(st + G1_A_OFF + soff, g_flat_h + goff, sz);
            int n = col0 + r;
            size_t boff = (size_t)n * 512 + c * 64 + li_c8 * 8;
            cp16z(st + G1_B_OFF + soff, g_wt_h + boff, 16u);
        }
        asm volatile("cp.async.commit_group;");
    };

    load_chunk(0);
    load_chunk(1);

    uint32_t aRow  = (uint32_t)(wm * 64 + (lane & 15));
    uint32_t aColB = (uint32_t)((lane >> 4) * 16);
    uint32_t bRow  = (uint32_t)(wn * 32 + ((lane >> 4) & 1) * 8 + (lane & 7));
    uint32_t bColB = (uint32_t)(((lane >> 3) & 1) * 16);

    for (int c = 0; c < 8; c++) {
        if (c < 7) { asm volatile("cp.async.wait_group 1;"); }
        else       { asm volatile("cp.async.wait_group 0;"); }
        __syncthreads();          // chunk c ready; all warps past compute c-1
        if (c + 2 < 8) load_chunk(c + 2);

        uint32_t st = sbase + (uint32_t)(c % 3) * G1_STAGE;
#pragma unroll
        for (int kk = 0; kk < 4; kk++) {
            uint32_t kb = (uint32_t)(kk * 32);
            uint32_t ah[4][4];
#pragma unroll
            for (int mi = 0; mi < 4; mi++) {
                uint32_t ad = st + G1_A_OFF + (aRow + mi * 16) * G1_PITCHB + kb + aColB;
                LDSM4(ah[mi][0], ah[mi][1], ah[mi][2], ah[mi][3], ad);
            }
            uint32_t bh[4][2];
#pragma unroll
            for (int nh = 0; nh < 2; nh++) {
                uint32_t bd = st + G1_B_OFF + (bRow + nh * 16) * G1_PITCHB + kb + bColB;
                uint32_t t0, t1, t2, t3;
                LDSM4(t0, t1, t2, t3, bd);
                bh[nh * 2][0] = t0; bh[nh * 2][1] = t1;
                bh[nh * 2 + 1][0] = t2; bh[nh * 2 + 1][1] = t3;
            }
#pragma unroll
            for (int mi = 0; mi < 4; mi++) {
#pragma unroll
                for (int ni = 0; ni < 4; ni++) {
                    MMA16816F16(acc[mi][ni], ah[mi], bh[ni]);
                }
            }
        }
    }

#pragma unroll
    for (int mi = 0; mi < 4; mi++) {
#pragma unroll
        for (int ni = 0; ni < 4; ni++) {
            int grow = row0 + wm * 64 + mi * 16 + (lane >> 2);
            int gcol = col0 + wn * 32 + ni * 8 + (lane & 3) * 2;
            if (grow < M) {
                __half2 h = __floats2half2_rn(acc[mi][ni][0], acc[mi][ni][1]);
                *(uint32_t*)(g_z1h + (size_t)grow * 256 + gcol) = *(uint32_t*)&h;
            }
            if (grow + 8 < M) {
                __half2 h = __floats2half2_rn(acc[mi][ni][2], acc[mi][ni][3]);
                *(uint32_t*)(g_z1h + (size_t)(grow + 8) * 256 + gcol) = *(uint32_t*)&h;
            }
        }
    }

#pragma unroll
    for (int ni = 0; ni < 4; ni++) {
#pragma unroll
        for (int jj = 0; jj < 2; jj++) {
            float s = 0.f, s2 = 0.f;
#pragma unroll
            for (int mi = 0; mi < 4; mi++) {
                float v0 = acc[mi][ni][jj], v1 = acc[mi][ni][jj + 2];
                s += v0 + v1; s2 += v0 * v0 + v1 * v1;
            }
#pragma unroll
            for (int o = 4; o <= 16; o <<= 1) {
                s  += __shfl_xor_sync(FULL, s, o);
                s2 += __shfl_xor_sync(FULL, s2, o);
            }
            if ((lane >> 2) == 0) {
                int col = col0 + wn * 32 + ni * 8 + (lane & 3) * 2 + jj;
                atomicAdd(&g_stats1[col], s);
                atomicAdd(&g_stats1[256 + col], s2);
            }
        }
    }
}

// ---------------- GEMM2 (mma.sync fp16 single-pass): bn1 params computed in-kernel ----------------
#define G2_PITCHB  144
#define G2_A_OFF   0
#define G2_B_OFF   18432
#define G2_SMEM    27648

__global__ void __launch_bounds__(256, 2)
k_gemm2_mma(float* __restrict__ out,
            const float* __restrict__ bn1g, const float* __restrict__ bn1b,
            float invM, int M) {
    extern __shared__ __align__(16) char dsm2[];
    uint32_t sbase = smem_u32(dsm2);
    __shared__ float ss[128];
    __shared__ float sbn_sc[256], sbn_sh[256];
    const unsigned FULL = 0xffffffffu;

    int tid  = threadIdx.x;
    int lane = tid & 31;
    int wid  = tid >> 5;
    int row0 = blockIdx.x * 128;

    if (tid < 128) ss[tid] = 0.f;
    {
        float mu  = g_stats1[tid] * invM;
        float var = g_stats1[256 + tid] * invM - mu * mu;
        float s = bn1g[tid] * rsqrtf(var + 0.001f);
        sbn_sc[tid] = s;
        sbn_sh[tid] = bn1b[tid] - mu * s;
    }

    float acc[8][4] = {};

    uint32_t aRow  = (uint32_t)(wid * 16 + (lane & 15));
    uint32_t aColB = (uint32_t)((lane >> 4) * 16);
    uint32_t bRowB = (uint32_t)(((lane >> 4) & 1) * 8 + (lane & 7));
    uint32_t bColB = (uint32_t)(((lane >> 3) & 1) * 16);

    for (int c = 0; c < 4; c++) {
        __syncthreads();
        {
            int f4 = tid & 3;
            int colb = f4 * 16;
#pragma unroll
            for (int half = 0; half < 2; half++) {
                int r = (tid >> 2) + half * 64;
                int gr = row0 + r;
                uint32_t hv[8] = {};
                if (gr < M) {
                    const uint4* src = (const uint4*)(g_z1h + (size_t)gr * 256 + c * 64 + colb);
                    *(uint4*)&hv[0] = src[0];
                    *(uint4*)&hv[4] = src[1];
                }
                uint32_t outp[8];
#pragma unroll
                for (int p = 0; p < 8; p++) {
                    __half2 h2 = *(__half2*)&hv[p];
                    float2 v = __half22float2(h2);
                    int col = c * 64 + colb + p * 2;
                    float y0 = (gr < M) ? fmaxf(v.x * sbn_sc[col] + sbn_sh[col], 0.f) : 0.f;
                    float y1 = (gr < M) ? fmaxf(v.y * sbn_sc[col + 1] + sbn_sh[col + 1], 0.f) : 0.f;
                    __half2 o = __floats2half2_rn(y0, y1);
                    outp[p] = *(uint32_t*)&o;
                }
                uint32_t off = (uint32_t)(r * G2_PITCHB + colb * 2);
                *(uint4*)(dsm2 + G2_A_OFF + off)      = *(uint4*)&outp[0];
                *(uint4*)(dsm2 + G2_A_OFF + off + 16) = *(uint4*)&outp[4];
            }
        }
        {
            int n = tid >> 2;
            int kg = (tid & 3) * 16;
            const uint4* gh = (const uint4*)(g_w2t_h + (size_t)n * 256 + c * 64 + kg);
            uint32_t off = (uint32_t)(n * G2_PITCHB + kg * 2);
            *(uint4*)(dsm2 + G2_B_OFF + off)      = gh[0];
            *(uint4*)(dsm2 + G2_B_OFF + off + 16) = gh[1];
        }
        __syncthreads();

#pragma unroll
        for (int kk = 0; kk < 4; kk++) {
            uint32_t kb = (uint32_t)(kk * 32);
            uint32_t ah[4];
            {
                uint32_t ad = sbase + G2_A_OFF + aRow * G2_PITCHB + kb + aColB;
                LDSM4(ah[0], ah[1], ah[2], ah[3], ad);
            }
            uint32_t bh[8][2];
#pragma unroll
            for (int nh = 0; nh < 4; nh++) {
                uint32_t bd = sbase + G2_B_OFF + (nh * 16 + bRowB) * G2_PITCHB + kb + bColB;
                uint32_t t0, t1, t2, t3;
                LDSM4(t0, t1, t2, t3, bd);
                bh[nh * 2][0] = t0; bh[nh * 2][1] = t1;
                bh[nh * 2 + 1][0] = t2; bh[nh * 2 + 1][1] = t3;
            }
#pragma unroll
            for (int ni = 0; ni < 8; ni++) {
                MMA16816F16(acc[ni], ah, bh[ni]);
            }
        }
    }

    int grow = row0 + wid * 16 + (lane >> 2);
#pragma unroll
    for (int ni = 0; ni < 8; ni++) {
        int gcol = ni * 8 + (lane & 3) * 2;
        if (grow < M)
            *(float2*)(out + (size_t)grow * 64 + gcol) = make_float2(acc[ni][0], acc[ni][1]);
        if (grow + 8 < M)
            *(float2*)(out + (size_t)(grow + 8) * 64 + gcol) = make_float2(acc[ni][2], acc[ni][3]);
    }

#pragma unroll
    for (int ni = 0; ni < 8; ni++) {
#pragma unroll
        for (int jj = 0; jj < 2; jj++) {
            float s = acc[ni][jj] + acc[ni][jj + 2];
            float s2 = acc[ni][jj] * acc[ni][jj] + acc[ni][jj + 2] * acc[ni][jj + 2];
#pragma unroll
            for (int o = 4; o <= 16; o <<= 1) {
                s  += __shfl_xor_sync(FULL, s, o);
                s2 += __shfl_xor_sync(FULL, s2, o);
            }
            if ((lane >> 2) == 0) {
                int col = ni * 8 + (lane & 3) * 2 + jj;
                atomicAdd(&ss[col], s);
                atomicAdd(&ss[64 + col], s2);
            }
        }
    }
    __syncthreads();
    if (tid < 128) atomicAdd(&g_stats2[tid], ss[tid]);
}

// ---------------- final: bn2 params computed in-kernel + normalize ----------------
__global__ void k_final(float* __restrict__ out,
                        const float* __restrict__ bn2g, const float* __restrict__ bn2b,
                        float invM, int n) {
    __shared__ float sc[64], sh[64];
    if (threadIdx.x < 64) {
        int c = threadIdx.x;
        float mu  = g_stats2[c] * invM;
        float var = g_stats2[64 + c] * invM - mu * mu;
        float s = bn2g[c] * rsqrtf(var + 0.001f);
        sc[c] = s;
        sh[c] = bn2b[c] - mu * s;
    }
    __syncthreads();
    int i = blockIdx.x * blockDim.x + threadIdx.x;
    if (i < n) {
        int c = i & 63;
        out[i] = fmaxf(out[i] * sc[c] + sh[c], 0.f);
    }
}

// ---------------- launcher ----------------
extern "C" void kernel_launch(void* const* d_in, const int* in_sizes, int n_in,
                              void* d_out, int out_size) {
    const float* vf      = (const float*)d_in[0];
    const int*   coords  = (const int*)d_in[1];
    const int*   inv     = (const int*)d_in[3];
    const int*   cnt     = (const int*)d_in[4];
    const float* up_w1   = (const float*)d_in[5];
    const float* up_b1   = (const float*)d_in[6];
    const float* up_w2   = (const float*)d_in[7];
    const float* up_b2   = (const float*)d_in[8];
    const float* ca_w1   = (const float*)d_in[9];
    const float* ca_w2   = (const float*)d_in[10];
    const float* sa_conv = (const float*)d_in[11];
    const float* bs_w1   = (const float*)d_in[12];
    const float* bn1_g   = (const float*)d_in[13];
    const float* bn1_b   = (const float*)d_in[14];
    const float* bs_w2   = (const float*)d_in[15];
    const float* bn2_g   = (const float*)d_in[16];
    const float* bn2_b   = (const float*)d_in[17];

    int Nv = in_sizes[0] / 5;
    int U  = in_sizes[2];
    int M  = out_size / 64;
    if (M <= 0) return;

    int nwin = U * 8;
    k_init<<<(nwin + 255) / 256, 256>>>(nwin, bs_w1, bs_w2);
    k_scatter<<<(Nv + 255) / 256, 256>>>(coords, inv, Nv);

    int NB = (U + 1023) / 1024;
    k_count<<<NB, 256>>>(cnt, U);
    k_compact<<<NB, 256>>>(cnt, U);

    {
        cudaFuncSetAttribute(k_rows2, cudaFuncAttributeMaxDynamicSharedMemorySize, R_SMEM);
        k_rows2<<<(M + 63) / 64, 256, R_SMEM>>>(vf, up_w1, up_b1, up_w2, up_b2,
                                                ca_w1, ca_w2, sa_conv, M);
    }

    {
        int dynsmem = 3 * G1_STAGE;
        cudaFuncSetAttribute(k_gemm1_mma, cudaFuncAttributeMaxDynamicSharedMemorySize, dynsmem);
        dim3 g1(2, (M + 127) / 128);
        k_gemm1_mma<<<g1, 256, dynsmem>>>(M);
    }

    {
        cudaFuncSetAttribute(k_gemm2_mma, cudaFuncAttributeMaxDynamicSharedMemorySize, G2_SMEM);
        k_gemm2_mma<<<(M + 127) / 128, 256, G2_SMEM>>>((float*)d_out, bn1_g, bn1_b,
                                                       1.f / (float)M, M);
    }
    k_final<<<(M * 64 + 255) / 256, 256>>>((float*)d_out, bn2_g, bn2_b,
                                           1.f / (float)M, M * 64);
}

// round 17
// speedup vs baseline: 1.2873x; 1.0333x over previous
#include <cuda_runtime.h>
#include <cuda_bf16.h>
#include <cuda_fp16.h>
#include <math.h>
#include <stdint.h>

// ---------------- static scratch (allocation-free) ----------------
#define UMAX 200000
__device__ int   g_winner[UMAX * 8];
__device__ int   g_selrows[UMAX];
__device__ int   g_bsum[256];
__device__ __align__(16) __half g_flat_h[(size_t)UMAX * 512];
__device__ __align__(16) __half g_wt_h[256 * 512];
__device__ __align__(16) __half g_w2t_h[64 * 256];
__device__ __align__(16) __half g_z1h[(size_t)UMAX * 256];
__device__ __align__(16) float g_stats1[512];   // sum[256] | sumsq[256]
__device__ __align__(16) float g_stats2[128];   // sum[64]  | sumsq[64]

__device__ __forceinline__ uint32_t smem_u32(const void* p) {
    uint32_t a;
    asm("{ .reg .u64 t; cvta.to.shared.u64 t, %1; cvt.u32.u64 %0, t; }" : "=r"(a) : "l"(p));
    return a;
}

// ---------------- kernel 1: init + weight prep + count (merged) ----------------
__global__ void k_init(int nwin, const float* __restrict__ W1, const float* __restrict__ W2,
                       const int* __restrict__ cnt, int U, int NB) {
    __shared__ int s[256];
    int bid = blockIdx.x;
    int tid = threadIdx.x;
    int i = bid * 256 + tid;
    if (i < nwin) g_winner[i] = -1;
    if (i < 512)  g_stats1[i] = 0.f;
    if (i < 128)  g_stats2[i] = 0.f;
    if (i < 131072) {
        int n = i >> 9, k = i & 511;
        g_wt_h[i] = __float2half(W1[(size_t)k * 256 + n]);
    }
    if (i < 16384) {
        int n = i >> 8, k = i & 255;
        g_w2t_h[i] = __float2half(W2[(size_t)k * 64 + n]);
    }
    // count: first NB blocks each handle 1024 cnt entries
    if (bid < NB) {
        int base = bid * 1024;
        int c = 0;
        for (int t = tid; t < 1024; t += 256) {
            int u = base + t;
            if (u < U && cnt[u] >= 2) c++;
        }
        s[tid] = c;
        __syncthreads();
        for (int o = 128; o > 0; o >>= 1) {
            if (tid < o) s[tid] += s[tid + o];
            __syncthreads();
        }
        if (tid == 0) g_bsum[bid] = s[0];
    }
}

// ---------------- kernel 2: scatter + compact (merged) ----------------
__global__ void k_scatter(const int* __restrict__ coords, const int* __restrict__ inv, int Nv,
                          const int* __restrict__ cnt, int U, int NSB) {
    int bid = blockIdx.x;
    int tid = threadIdx.x;
    if (bid < NSB) {
        int i = bid * 256 + tid;
        if (i < Nv) {
            int z = coords[(size_t)i * 4 + 1];
            int u = inv[i];
            atomicMax(&g_winner[(size_t)u * 8 + z], i);
        }
        return;
    }
    // compact role
    __shared__ int s[256];
    __shared__ int spre[256];
    __shared__ int s_off;
    int cb = bid - NSB;
    {
        int acc = 0;
        for (int i = tid; i < cb; i += 256) acc += g_bsum[i];
        spre[tid] = acc;
        __syncthreads();
        for (int o = 128; o > 0; o >>= 1) {
            if (tid < o) spre[tid] += spre[tid + o];
            __syncthreads();
        }
        if (tid == 0) s_off = spre[0];
        __syncthreads();
    }
    int base = cb * 1024 + tid * 4;
    int flags[4]; int c = 0;
    for (int q = 0; q < 4; q++) {
        int u = base + q;
        flags[q] = (u < U && cnt[u] >= 2) ? 1 : 0;
        c += flags[q];
    }
    s[tid] = c;
    __syncthreads();
    for (int o = 1; o < 256; o <<= 1) {
        int v = (tid >= o) ? s[tid - o] : 0;
        __syncthreads();
        s[tid] += v;
        __syncthreads();
    }
    int off = s_off + s[tid] - c;
    for (int q = 0; q < 4; q++) {
        if (flags[q]) g_selrows[off++] = base + q;
    }
}

// ---------------- common mma macros ----------------
#define LDSM4(R0, R1, R2, R3, ADDR) \
    asm volatile("ldmatrix.sync.aligned.m8n8.x4.shared.b16 {%0,%1,%2,%3}, [%4];" \
                 : "=r"(R0), "=r"(R1), "=r"(R2), "=r"(R3) : "r"(ADDR))

#define MMA16816F16(D, A, B) \
    asm volatile("mma.sync.aligned.m16n8k16.row.col.f32.f16.f16.f32 " \
                 "{%0,%1,%2,%3}, {%4,%5,%6,%7}, {%8,%9}, {%0,%1,%2,%3};" \
                 : "+f"((D)[0]), "+f"((D)[1]), "+f"((D)[2]), "+f"((D)[3]) \
                 : "r"((A)[0]), "r"((A)[1]), "r"((A)[2]), "r"((A)[3]), \
                   "r"((B)[0]), "r"((B)[1]))

__device__ __forceinline__ void cp16z(uint32_t saddr, const void* gaddr, uint32_t sz) {
    asm volatile("cp.async.cg.shared.global [%0], [%1], 16, %2;"
                 :: "r"(saddr), "l"(gaddr), "r"(sz));
}

// ---------------- k_rows2: slot MLP (tensorized hi/lo) + CBAM + flatten ----------------
#define R_W2H   0
#define R_W2L   5120
#define R_WARP0 10240
#define R_WSTR  7488
#define R_HIDH  0
#define R_HIDL  1280
#define R_XBUF  2560
#define R_FEAT  7168
#define R_BC    70144
#define R_SMEM  75328

__global__ void __launch_bounds__(256, 2)
k_rows2(const float* __restrict__ vf,
        const float* __restrict__ w1, const float* __restrict__ b1,
        const float* __restrict__ w2g, const float* __restrict__ b2,
        const float* __restrict__ caw1, const float* __restrict__ caw2,
        const float* __restrict__ saconv, int M)
{
    extern __shared__ __align__(16) char dsm[];
    uint32_t sbase = smem_u32(dsm);
    float* bc = (float*)(dsm + R_BC);
    float* sw1f  = bc + 0;
    float* sb1f  = bc + 160;
    float* sb2f  = bc + 192;
    float* scw1f = bc + 256;
    float* scw2f = bc + 768;
    float* sconvf = bc + 1280;

    const unsigned FULL = 0xffffffffu;
    int tid  = threadIdx.x;
    int wid  = tid >> 5;
    int lane = tid & 31;
    int row0 = blockIdx.x * 64;

    for (int i = tid; i < 160; i += 256) sw1f[i] = w1[i];
    if (tid < 32) sb1f[tid] = b1[tid];
    if (tid < 64) sb2f[tid] = b2[tid];
    for (int i = tid; i < 512; i += 256) scw1f[i] = caw1[i];
    for (int i = tid; i < 512; i += 256) scw2f[i] = caw2[i];
    if (tid < 14) sconvf[tid] = saconv[tid];

    for (int i = tid; i < 2048; i += 256) {
        int n = i >> 5, k = i & 31;
        float w = w2g[k * 64 + n];
        __half hh = __float2half(w);
        float lo = w - __half2float(hh);
        *(__half*)(dsm + R_W2H + n * 80 + k * 2) = hh;
        *(__half*)(dsm + R_W2L + n * 80 + k * 2) = __float2half(lo);
    }
    __syncthreads();

    uint32_t wbase = sbase + R_WARP0 + (uint32_t)wid * R_WSTR;
    float* featp = (float*)(dsm + R_WARP0 + wid * R_WSTR + R_FEAT);
    float* xb    = (float*)(dsm + R_WARP0 + wid * R_WSTR + R_XBUF);
    __half* hidh = (__half*)(dsm + R_WARP0 + wid * R_WSTR + R_HIDH);
    __half* hidl = (__half*)(dsm + R_WARP0 + wid * R_WSTR + R_HIDL);

    uint32_t aColB = (uint32_t)((lane >> 4) * 16);
    uint32_t aRowO = (uint32_t)((lane & 15) * 80);
    uint32_t bRowB = (uint32_t)(((lane >> 4) & 1) * 8 + (lane & 7));
    uint32_t bColB = (uint32_t)(((lane >> 3) & 1) * 16);

    for (int rp = 0; rp < 4; rp++) {
        int j0 = row0 + wid * 8 + rp * 2;
        if (j0 >= M) break;

#pragma unroll
        for (int rr = 0; rr < 2; rr++) {
            int j = j0 + rr;
            int valid = (j < M);
            int u = valid ? g_selrows[j] : 0;
            int wv = (valid && lane < 8) ? g_winner[(size_t)u * 8 + lane] : -1;
#pragma unroll
            for (int q = 0; q < 2; q++) {
                int t = lane + q * 32;
                int tv = (t < 40);
                int zz = tv ? (t / 5) : 0;
                int f  = t - zz * 5;
                int w = __shfl_sync(FULL, wv, zz);
                if (tv) featp[rr * 40 + t] = (w >= 0) ? vf[(size_t)w * 5 + f] : 0.f;
            }
        }
        __syncwarp();

#pragma unroll
        for (int z = 0; z < 16; z++) {
            const float* ft = featp + (z >> 3) * 40 + (z & 7) * 5;
            float a = sb1f[lane];
#pragma unroll
            for (int f = 0; f < 5; f++) a += ft[f] * sw1f[f * 32 + lane];
            a = fmaxf(a, 0.f);
            __half hh = __float2half(a);
            float lo = a - __half2float(hh);
            hidh[z * 40 + lane] = hh;
            hidl[z * 40 + lane] = __float2half(lo);
        }
        __syncwarp();

        float acc[8][4] = {};
#pragma unroll
        for (int kk = 0; kk < 2; kk++) {
            uint32_t kb = (uint32_t)(kk * 32);
            uint32_t ah[4], al[4];
            LDSM4(ah[0], ah[1], ah[2], ah[3], wbase + R_HIDH + aRowO + kb + aColB);
            LDSM4(al[0], al[1], al[2], al[3], wbase + R_HIDL + aRowO + kb + aColB);
            uint32_t bh[8][2], bl[8][2];
#pragma unroll
            for (int nh = 0; nh < 4; nh++) {
                uint32_t rofs = (uint32_t)(nh * 16 + bRowB) * 80 + kb + bColB;
                uint32_t t0, t1, t2, t3;
                LDSM4(t0, t1, t2, t3, sbase + R_W2H + rofs);
                bh[nh * 2][0] = t0; bh[nh * 2][1] = t1;
                bh[nh * 2 + 1][0] = t2; bh[nh * 2 + 1][1] = t3;
                LDSM4(t0, t1, t2, t3, sbase + R_W2L + rofs);
                bl[nh * 2][0] = t0; bl[nh * 2][1] = t1;
                bl[nh * 2 + 1][0] = t2; bl[nh * 2 + 1][1] = t3;
            }
#pragma unroll
            for (int ni = 0; ni < 8; ni++) {
                MMA16816F16(acc[ni], ah, bh[ni]);
                MMA16816F16(acc[ni], ah, bl[ni]);
                MMA16816F16(acc[ni], al, bh[ni]);
            }
        }

        {
            int r0 = lane >> 2, c0 = (lane & 3) * 2;
#pragma unroll
            for (int ni = 0; ni < 8; ni++) {
                *(float2*)&xb[r0 * 72 + ni * 8 + c0]       = make_float2(acc[ni][0], acc[ni][1]);
                *(float2*)&xb[(r0 + 8) * 72 + ni * 8 + c0] = make_float2(acc[ni][2], acc[ni][3]);
            }
        }
        __syncwarp();

#pragma unroll
        for (int rr = 0; rr < 2; rr++) {
            int j = j0 + rr;
            float x0[8], x1[8];
#pragma unroll
            for (int z = 0; z < 8; z++) {
                x0[z] = xb[(rr * 8 + z) * 72 + lane]      + sb2f[lane];
                x1[z] = xb[(rr * 8 + z) * 72 + lane + 32] + sb2f[lane + 32];
            }

            float m0 = 0.f, m1 = 0.f, q0 = -3.4e38f, q1 = -3.4e38f;
#pragma unroll
            for (int z = 0; z < 8; z++) {
                m0 += x0[z]; m1 += x1[z];
                q0 = fmaxf(q0, x0[z]); q1 = fmaxf(q1, x1[z]);
            }
            m0 *= 0.125f; m1 *= 0.125f;

            float s8[8];
#pragma unroll
            for (int r8 = 0; r8 < 8; r8++) {
                float pm = m0 * scw1f[lane * 8 + r8] + m1 * scw1f[(lane + 32) * 8 + r8];
                float px = q0 * scw1f[lane * 8 + r8] + q1 * scw1f[(lane + 32) * 8 + r8];
#pragma unroll
                for (int o = 16; o > 0; o >>= 1) {
                    pm += __shfl_xor_sync(FULL, pm, o);
                    px += __shfl_xor_sync(FULL, px, o);
                }
                s8[r8] = fmaxf(pm, 0.f) + fmaxf(px, 0.f);
            }

            float a0 = 0.f, a1 = 0.f;
#pragma unroll
            for (int r8 = 0; r8 < 8; r8++) {
                a0 += s8[r8] * scw2f[r8 * 64 + lane];
                a1 += s8[r8] * scw2f[r8 * 64 + lane + 32];
            }
            float ca0 = 1.f / (1.f + expf(-a0));
            float ca1 = 1.f / (1.f + expf(-a1));
#pragma unroll
            for (int z = 0; z < 8; z++) { x0[z] *= ca0; x1[z] *= ca1; }

            float szm[8], szx[8];
#pragma unroll
            for (int z = 0; z < 8; z++) {
                float s = x0[z] + x1[z];
                float m = fmaxf(x0[z], x1[z]);
#pragma unroll
                for (int o = 16; o > 0; o >>= 1) {
                    s += __shfl_xor_sync(FULL, s, o);
                    m = fmaxf(m, __shfl_xor_sync(FULL, m, o));
                }
                szm[z] = s * (1.f / 64.f);
                szx[z] = m;
            }

            float sav = 0.f;
            if (lane < 8) {
                float acc2 = 0.f;
#pragma unroll
                for (int t = 0; t < 7; t++) {
                    int p = lane + t - 3;
                    if (p >= 0 && p < 8) acc2 += szm[p] * sconvf[t] + szx[p] * sconvf[7 + t];
                }
                sav = 1.f / (1.f + expf(-acc2));
            }
            float sa[8];
#pragma unroll
            for (int z = 0; z < 8; z++) sa[z] = __shfl_sync(FULL, sav, z);

            if (j < M) {
                size_t base = (size_t)j * 512;
                uint32_t ph[4];
#pragma unroll
                for (int z2 = 0; z2 < 4; z2++) {
                    __half2 h2 = __floats2half2_rn(x0[2 * z2] * sa[2 * z2], x0[2 * z2 + 1] * sa[2 * z2 + 1]);
                    ph[z2] = *(uint32_t*)&h2;
                }
                *(uint4*)&g_flat_h[base + lane * 8] = *(uint4*)ph;
#pragma unroll
                for (int z2 = 0; z2 < 4; z2++) {
                    __half2 h2 = __floats2half2_rn(x1[2 * z2] * sa[2 * z2], x1[2 * z2 + 1] * sa[2 * z2 + 1]);
                    ph[z2] = *(uint32_t*)&h2;
                }
                *(uint4*)&g_flat_h[base + (lane + 32) * 8] = *(uint4*)ph;
            }
        }
        __syncwarp();
    }
}

// ---------------- GEMM1 (mma.sync fp16, 3-stage pipeline) + fused bn1 stats ----------------
#define G1_PITCHB  144
#define G1_A_OFF   0
#define G1_B_OFF   18432
#define G1_STAGE   36864

__global__ void __launch_bounds__(256, 2)
k_gemm1_mma(int M) {
    extern __shared__ __align__(16) char dsm[];
    uint32_t sbase = smem_u32(dsm);
    const unsigned FULL = 0xffffffffu;

    int tid  = threadIdx.x;
    int lane = tid & 31;
    int wid  = tid >> 5;
    int wm = wid & 1;
    int wn = wid >> 1;
    int row0 = blockIdx.y * 128;
    int col0 = blockIdx.x * 128;

    int li_r  = tid >> 3;
    int li_c8 = tid & 7;

    float acc[4][4][4] = {};

    auto load_chunk = [&](int c) {
        uint32_t st = sbase + (uint32_t)(c % 3) * G1_STAGE;
#pragma unroll
        for (int it = 0; it < 4; it++) {
            int r = li_r + it * 32;
            int gr = row0 + r;
            uint32_t soff = (uint32_t)(r * G1_PITCHB + li_c8 * 16);
            size_t goff = (size_t)gr * 512 + c * 64 + li_c8 * 8;
            uint32_t sz = (gr < M) ? 16u : 0u;
            cp16z(st + G1_A_OFF + soff, g_flat_h + goff, sz);
            int n = col0 + r;
            size_t boff = (size_t)n * 512 + c * 64 + li_c8 * 8;
            cp16z(st + G1_B_OFF + soff, g_wt_h + boff, 16u);
        }
        asm volatile("cp.async.commit_group;");
    };

    load_chunk(0);
    load_chunk(1);

    uint32_t aRow  = (uint32_t)(wm * 64 + (lane & 15));
    uint32_t aColB = (uint32_t)((lane >> 4) * 16);
    uint32_t bRow  = (uint32_t)(wn * 32 + ((lane >> 4) & 1) * 8 + (lane & 7));
    uint32_t bColB = (uint32_t)(((lane >> 3) & 1) * 16);

    for (int c = 0; c < 8; c++) {
        if (c < 7) { asm volatile("cp.async.wait_group 1;"); }
        else       { asm volatile("cp.async.wait_group 0;"); }
        __syncthreads();
        if (c + 2 < 8) load_chunk(c + 2);

        uint32_t st = sbase + (uint32_t)(c % 3) * G1_STAGE;
#pragma unroll
        for (int kk = 0; kk < 4; kk++) {
            uint32_t kb = (uint32_t)(kk * 32);
            uint32_t ah[4][4];
#pragma unroll
            for (int mi = 0; mi < 4; mi++) {
                uint32_t ad = st + G1_A_OFF + (aRow + mi * 16) * G1_PITCHB + kb + aColB;
                LDSM4(ah[mi][0], ah[mi][1], ah[mi][2], ah[mi][3], ad);
            }
            uint32_t bh[4][2];
#pragma unroll
            for (int nh = 0; nh < 2; nh++) {
                uint32_t bd = st + G1_B_OFF + (bRow + nh * 16) * G1_PITCHB + kb + bColB;
                uint32_t t0, t1, t2, t3;
                LDSM4(t0, t1, t2, t3, bd);
                bh[nh * 2][0] = t0; bh[nh * 2][1] = t1;
                bh[nh * 2 + 1][0] = t2; bh[nh * 2 + 1][1] = t3;
            }
#pragma unroll
            for (int mi = 0; mi < 4; mi++) {
#pragma unroll
                for (int ni = 0; ni < 4; ni++) {
                    MMA16816F16(acc[mi][ni], ah[mi], bh[ni]);
                }
            }
        }
    }

#pragma unroll
    for (int mi = 0; mi < 4; mi++) {
#pragma unroll
        for (int ni = 0; ni < 4; ni++) {
            int grow = row0 + wm * 64 + mi * 16 + (lane >> 2);
            int gcol = col0 + wn * 32 + ni * 8 + (lane & 3) * 2;
            if (grow < M) {
                __half2 h = __floats2half2_rn(acc[mi][ni][0], acc[mi][ni][1]);
                *(uint32_t*)(g_z1h + (size_t)grow * 256 + gcol) = *(uint32_t*)&h;
            }
            if (grow + 8 < M) {
                __half2 h = __floats2half2_rn(acc[mi][ni][2], acc[mi][ni][3]);
                *(uint32_t*)(g_z1h + (size_t)(grow + 8) * 256 + gcol) = *(uint32_t*)&h;
            }
        }
    }

#pragma unroll
    for (int ni = 0; ni < 4; ni++) {
#pragma unroll
        for (int jj = 0; jj < 2; jj++) {
            float s = 0.f, s2 = 0.f;
#pragma unroll
            for (int mi = 0; mi < 4; mi++) {
                float v0 = acc[mi][ni][jj], v1 = acc[mi][ni][jj + 2];
                s += v0 + v1; s2 += v0 * v0 + v1 * v1;
            }
#pragma unroll
            for (int o = 4; o <= 16; o <<= 1) {
                s  += __shfl_xor_sync(FULL, s, o);
                s2 += __shfl_xor_sync(FULL, s2, o);
            }
            if ((lane >> 2) == 0) {
                int col = col0 + wn * 32 + ni * 8 + (lane & 3) * 2 + jj;
                atomicAdd(&g_stats1[col], s);
                atomicAdd(&g_stats1[256 + col], s2);
            }
        }
    }
}

// ---------------- GEMM2 (mma.sync fp16 single-pass): bn1 params computed in-kernel ----------------
#define G2_PITCHB  144
#define G2_A_OFF   0
#define G2_B_OFF   18432
#define G2_SMEM    27648

__global__ void __launch_bounds__(256, 2)
k_gemm2_mma(float* __restrict__ out,
            const float* __restrict__ bn1g, const float* __restrict__ bn1b,
            float invM, int M) {
    extern __shared__ __align__(16) char dsm2[];
    uint32_t sbase = smem_u32(dsm2);
    __shared__ float ss[128];
    __shared__ float sbn_sc[256], sbn_sh[256];
    const unsigned FULL = 0xffffffffu;

    int tid  = threadIdx.x;
    int lane = tid & 31;
    int wid  = tid >> 5;
    int row0 = blockIdx.x * 128;

    if (tid < 128) ss[tid] = 0.f;
    {
        float mu  = g_stats1[tid] * invM;
        float var = g_stats1[256 + tid] * invM - mu * mu;
        float s = bn1g[tid] * rsqrtf(var + 0.001f);
        sbn_sc[tid] = s;
        sbn_sh[tid] = bn1b[tid] - mu * s;
    }

    float acc[8][4] = {};

    uint32_t aRow  = (uint32_t)(wid * 16 + (lane & 15));
    uint32_t aColB = (uint32_t)((lane >> 4) * 16);
    uint32_t bRowB = (uint32_t)(((lane >> 4) & 1) * 8 + (lane & 7));
    uint32_t bColB = (uint32_t)(((lane >> 3) & 1) * 16);

    for (int c = 0; c < 4; c++) {
        __syncthreads();
        {
            int f4 = tid & 3;
            int colb = f4 * 16;
#pragma unroll
            for (int half = 0; half < 2; half++) {
                int r = (tid >> 2) + half * 64;
                int gr = row0 + r;
                uint32_t hv[8] = {};
                if (gr < M) {
                    const uint4* src = (const uint4*)(g_z1h + (size_t)gr * 256 + c * 64 + colb);
                    *(uint4*)&hv[0] = src[0];
                    *(uint4*)&hv[4] = src[1];
                }
                uint32_t outp[8];
#pragma unroll
                for (int p = 0; p < 8; p++) {
                    __half2 h2 = *(__half2*)&hv[p];
                    float2 v = __half22float2(h2);
                    int col = c * 64 + colb + p * 2;
                    float y0 = (gr < M) ? fmaxf(v.x * sbn_sc[col] + sbn_sh[col], 0.f) : 0.f;
                    float y1 = (gr < M) ? fmaxf(v.y * sbn_sc[col + 1] + sbn_sh[col + 1], 0.f) : 0.f;
                    __half2 o = __floats2half2_rn(y0, y1);
                    outp[p] = *(uint32_t*)&o;
                }
                uint32_t off = (uint32_t)(r * G2_PITCHB + colb * 2);
                *(uint4*)(dsm2 + G2_A_OFF + off)      = *(uint4*)&outp[0];
                *(uint4*)(dsm2 + G2_A_OFF + off + 16) = *(uint4*)&outp[4];
            }
        }
        {
            int n = tid >> 2;
            int kg = (tid & 3) * 16;
            const uint4* gh = (const uint4*)(g_w2t_h + (size_t)n * 256 + c * 64 + kg);
            uint32_t off = (uint32_t)(n * G2_PITCHB + kg * 2);
            *(uint4*)(dsm2 + G2_B_OFF + off)      = gh[0];
            *(uint4*)(dsm2 + G2_B_OFF + off + 16) = gh[1];
        }
        __syncthreads();

#pragma unroll
        for (int kk = 0; kk < 4; kk++) {
            uint32_t kb = (uint32_t)(kk * 32);
            uint32_t ah[4];
            {
                uint32_t ad = sbase + G2_A_OFF + aRow * G2_PITCHB + kb + aColB;
                LDSM4(ah[0], ah[1], ah[2], ah[3], ad);
            }
            uint32_t bh[8][2];
#pragma unroll
            for (int nh = 0; nh < 4; nh++) {
                uint32_t bd = sbase + G2_B_OFF + (nh * 16 + bRowB) * G2_PITCHB + kb + bColB;
                uint32_t t0, t1, t2, t3;
                LDSM4(t0, t1, t2, t3, bd);
                bh[nh * 2][0] = t0; bh[nh * 2][1] = t1;
                bh[nh * 2 + 1][0] = t2; bh[nh * 2 + 1][1] = t3;
            }
#pragma unroll
            for (int ni = 0; ni < 8; ni++) {
                MMA16816F16(acc[ni], ah, bh[ni]);
            }
        }
    }

    int grow = row0 + wid * 16 + (lane >> 2);
#pragma unroll
    for (int ni = 0; ni < 8; ni++) {
        int gcol = ni * 8 + (lane & 3) * 2;
        if (grow < M)
            *(float2*)(out + (size_t)grow * 64 + gcol) = make_float2(acc[ni][0], acc[ni][1]);
        if (grow + 8 < M)
            *(float2*)(out + (size_t)(grow + 8) * 64 + gcol) = make_float2(acc[ni][2], acc[ni][3]);
    }

#pragma unroll
    for (int ni = 0; ni < 8; ni++) {
#pragma unroll
        for (int jj = 0; jj < 2; jj++) {
            float s = acc[ni][jj] + acc[ni][jj + 2];
            float s2 = acc[ni][jj] * acc[ni][jj] + acc[ni][jj + 2] * acc[ni][jj + 2];
#pragma unroll
            for (int o = 4; o <= 16; o <<= 1) {
                s  += __shfl_xor_sync(FULL, s, o);
                s2 += __shfl_xor_sync(FULL, s2, o);
            }
            if ((lane >> 2) == 0) {
                int col = ni * 8 + (lane & 3) * 2 + jj;
                atomicAdd(&ss[col], s);
                atomicAdd(&ss[64 + col], s2);
            }
        }
    }
    __syncthreads();
    if (tid < 128) atomicAdd(&g_stats2[tid], ss[tid]);
}

// ---------------- final: bn2 params computed in-kernel + normalize (float4) ----------------
__global__ void k_final(float* __restrict__ out,
                        const float* __restrict__ bn2g, const float* __restrict__ bn2b,
                        float invM, int n4) {
    __shared__ float sc[64], sh[64];
    if (threadIdx.x < 64) {
        int c = threadIdx.x;
        float mu  = g_stats2[c] * invM;
        float var = g_stats2[64 + c] * invM - mu * mu;
        float s = bn2g[c] * rsqrtf(var + 0.001f);
        sc[c] = s;
        sh[c] = bn2b[c] - mu * s;
    }
    __syncthreads();
    int i = blockIdx.x * blockDim.x + threadIdx.x;
    if (i < n4) {
        int c = (i * 4) & 63;
        float4 v = *(float4*)(out + (size_t)i * 4);
        v.x = fmaxf(v.x * sc[c]     + sh[c],     0.f);
        v.y = fmaxf(v.y * sc[c + 1] + sh[c + 1], 0.f);
        v.z = fmaxf(v.z * sc[c + 2] + sh[c + 2], 0.f);
        v.w = fmaxf(v.w * sc[c + 3] + sh[c + 3], 0.f);
        *(float4*)(out + (size_t)i * 4) = v;
    }
}

// ---------------- launcher ----------------
extern "C" void kernel_launch(void* const* d_in, const int* in_sizes, int n_in,
                              void* d_out, int out_size) {
    const float* vf      = (const float*)d_in[0];
    const int*   coords  = (const int*)d_in[1];
    const int*   inv     = (const int*)d_in[3];
    const int*   cnt     = (const int*)d_in[4];
    const float* up_w1   = (const float*)d_in[5];
    const float* up_b1   = (const float*)d_in[6];
    const float* up_w2   = (const float*)d_in[7];
    const float* up_b2   = (const float*)d_in[8];
    const float* ca_w1   = (const float*)d_in[9];
    const float* ca_w2   = (const float*)d_in[10];
    const float* sa_conv = (const float*)d_in[11];
    const float* bs_w1   = (const float*)d_in[12];
    const float* bn1_g   = (const float*)d_in[13];
    const float* bn1_b   = (const float*)d_in[14];
    const float* bs_w2   = (const float*)d_in[15];
    const float* bn2_g   = (const float*)d_in[16];
    const float* bn2_b   = (const float*)d_in[17];

    int Nv = in_sizes[0] / 5;
    int U  = in_sizes[2];
    int M  = out_size / 64;
    if (M <= 0) return;

    int nwin = U * 8;
    int NB = (U + 1023) / 1024;
    int initB = (nwin + 255) / 256;
    if (initB < NB) initB = NB;
    k_init<<<initB, 256>>>(nwin, bs_w1, bs_w2, cnt, U, NB);

    int NSB = (Nv + 255) / 256;
    k_scatter<<<NSB + NB, 256>>>(coords, inv, Nv, cnt, U, NSB);

    {
        cudaFuncSetAttribute(k_rows2, cudaFuncAttributeMaxDynamicSharedMemorySize, R_SMEM);
        k_rows2<<<(M + 63) / 64, 256, R_SMEM>>>(vf, up_w1, up_b1, up_w2, up_b2,
                                                ca_w1, ca_w2, sa_conv, M);
    }

    {
        int dynsmem = 3 * G1_STAGE;
        cudaFuncSetAttribute(k_gemm1_mma, cudaFuncAttributeMaxDynamicSharedMemorySize, dynsmem);
        dim3 g1(2, (M + 127) / 128);
        k_gemm1_mma<<<g1, 256, dynsmem>>>(M);
    }

    {
        cudaFuncSetAttribute(k_gemm2_mma, cudaFuncAttributeMaxDynamicSharedMemorySize, G2_SMEM);
        k_gemm2_mma<<<(M + 127) / 128, 256, G2_SMEM>>>((float*)d_out, bn1_g, bn1_b,
                                                       1.f / (float)M, M);
    }
    k_final<<<(M * 16 + 255) / 256, 256>>>((float*)d_out, bn2_g, bn2_b,
                                           1.f / (float)M, M * 16);
}